// round 2
// baseline (speedup 1.0000x reference)
#include <cuda_runtime.h>
#include <math.h>
#include <stdint.h>

#define B_    256
#define G_    16
#define GS_   588
#define HID_  1024
#define FEAT_ 2048
#define NSPLIT 16
#define KSPLIT ((G_ * FEAT_) / NSPLIT)   // 32768/16 = 2048

#define BM 128
#define BN 128
#define BK 8

// ---------------- scratch (device globals; no runtime alloc) ----------------
__device__ float g_h[(size_t)2 * B_ * G_ * HID_];        // [br*256+b][16384]
__device__ float g_f[(size_t)2 * B_ * G_ * FEAT_];       // [512][32768] interleaved o*16+g
__device__ float g_part[(size_t)NSPLIT * 2 * B_ * HID_]; // [split][512][1024]
__device__ float g_hg[(size_t)2 * B_ * HID_];            // [512][1024]
__device__ float g_o[(size_t)2 * B_ * FEAT_];            // [512][2048]
__device__ float g_scores[B_];

__device__ __forceinline__ float silu_f(float v) {
    return v / (1.0f + expf(-v));
}

// ---------------- shared 128x128x8 fp32 GEMM tile body ----------------
// A: [M,K] row-major (row stride lda), W: [K,N] row-major (row stride ldw).
// Computes acc[i][j] = sum_k A[m0+ty*8+i][k] * W[k][n0+tx*8+j].
__device__ __forceinline__ void sgemm_tile(
    const float* __restrict__ A, int lda,
    const float* __restrict__ W, int ldw,
    int K, int m0, int n0, float acc[8][8])
{
    __shared__ float As[BK][BM];
    __shared__ float Ws[BK][BN];

    const int tid  = threadIdx.x;      // 256 threads
    const int arow = tid >> 1;         // 0..127
    const int acol = (tid & 1) << 2;   // 0 or 4
    const int wrow = tid >> 5;         // 0..7
    const int wcol = (tid & 31) << 2;  // 0..124
    const int tx   = tid & 15;
    const int ty   = tid >> 4;

    const float* Aptr = A + (size_t)(m0 + arow) * lda;

    for (int k0 = 0; k0 < K; k0 += BK) {
        // load A sub-tile 128x8 (scalar, handles K not multiple of 8 / unaligned)
        #pragma unroll
        for (int i = 0; i < 4; ++i) {
            int kk = acol + i;
            int kg = k0 + kk;
            float v = 0.0f;
            if (kg < K) v = Aptr[kg];
            As[kk][arow] = v;
        }
        // load W sub-tile 8x128 (vectorized, coalesced)
        {
            float4 wv = make_float4(0.f, 0.f, 0.f, 0.f);
            if (k0 + wrow < K)
                wv = *reinterpret_cast<const float4*>(
                        W + (size_t)(k0 + wrow) * ldw + n0 + wcol);
            Ws[wrow][wcol + 0] = wv.x;
            Ws[wrow][wcol + 1] = wv.y;
            Ws[wrow][wcol + 2] = wv.z;
            Ws[wrow][wcol + 3] = wv.w;
        }
        __syncthreads();

        #pragma unroll
        for (int kk = 0; kk < BK; ++kk) {
            float ra[8], rb[8];
            #pragma unroll
            for (int i = 0; i < 8; ++i) ra[i] = As[kk][ty * 8 + i];
            #pragma unroll
            for (int j = 0; j < 8; ++j) rb[j] = Ws[kk][tx * 8 + j];
            #pragma unroll
            for (int i = 0; i < 8; ++i)
                #pragma unroll
                for (int j = 0; j < 8; ++j)
                    acc[i][j] = fmaf(ra[i], rb[j], acc[i][j]);
        }
        __syncthreads();
    }
}

// ---------------- stage 1: grouped fc1 (q & k branches) ----------------
// grid (2, 8, 32): z = branch*16 + group
__global__ __launch_bounds__(256) void k_grouped_fc1(
    const float* __restrict__ q,  const float* __restrict__ k,
    const float* __restrict__ Wq1, const float* __restrict__ bq1,
    const float* __restrict__ Wk1, const float* __restrict__ bk1)
{
    const int z  = blockIdx.z;
    const int br = z >> 4;
    const int g  = z & 15;

    const float* x    = (br ? k : q) + g * GS_;
    const float* W    = (br ? Wk1 : Wq1) + (size_t)g * GS_ * HID_;
    const float* bias = (br ? bk1 : bq1) + g * HID_;

    float acc[8][8];
    #pragma unroll
    for (int i = 0; i < 8; ++i)
        #pragma unroll
        for (int j = 0; j < 8; ++j) acc[i][j] = 0.0f;

    const int m0 = blockIdx.x * BM;
    const int n0 = blockIdx.y * BN;
    sgemm_tile(x, G_ * GS_, W, HID_, GS_, m0, n0, acc);

    float* C = g_h + (size_t)br * B_ * G_ * HID_ + g * HID_;
    const int tx = threadIdx.x & 15, ty = threadIdx.x >> 4;
    #pragma unroll
    for (int i = 0; i < 8; ++i) {
        int row = m0 + ty * 8 + i;
        #pragma unroll
        for (int j = 0; j < 8; ++j) {
            int col = n0 + tx * 8 + j;
            float v = acc[i][j] + bias[col];
            C[(size_t)row * (G_ * HID_) + col] = silu_f(v);
        }
    }
}

// ---------------- stage 2: grouped fc4 + interleaved store ----------------
// grid (2, 16, 32)
__global__ __launch_bounds__(256) void k_grouped_fc4(
    const float* __restrict__ Wq4, const float* __restrict__ bq4,
    const float* __restrict__ Wk4, const float* __restrict__ bk4)
{
    const int z  = blockIdx.z;
    const int br = z >> 4;
    const int g  = z & 15;

    const float* A    = g_h + (size_t)br * B_ * G_ * HID_ + g * HID_;
    const float* W    = (br ? Wk4 : Wq4) + (size_t)g * HID_ * FEAT_;
    const float* bias = (br ? bk4 : bq4) + g * FEAT_;

    float acc[8][8];
    #pragma unroll
    for (int i = 0; i < 8; ++i)
        #pragma unroll
        for (int j = 0; j < 8; ++j) acc[i][j] = 0.0f;

    const int m0 = blockIdx.x * BM;
    const int n0 = blockIdx.y * BN;
    sgemm_tile(A, G_ * HID_, W, FEAT_, HID_, m0, n0, acc);

    // qf[b, o*G + g] = silu(f[b,g,o])  (feature-major interleave)
    const int tx = threadIdx.x & 15, ty = threadIdx.x >> 4;
    #pragma unroll
    for (int i = 0; i < 8; ++i) {
        int row = m0 + ty * 8 + i;
        size_t rbase = (size_t)(br * B_ + row) * (G_ * FEAT_);
        #pragma unroll
        for (int j = 0; j < 8; ++j) {
            int col = n0 + tx * 8 + j;
            float v = acc[i][j] + bias[col];
            g_f[rbase + (size_t)col * G_ + g] = silu_f(v);
        }
    }
}

// ---------------- stage 3: global fc1, split-K (deterministic) ----------------
// grid (4, 8, NSPLIT): M=512 (q rows 0..255, k rows 256..511)
__global__ __launch_bounds__(256) void k_global_fc1_splitk(
    const float* __restrict__ Wg1)
{
    const int s = blockIdx.z;
    const float* A = g_f + s * KSPLIT;
    const float* W = Wg1 + (size_t)s * KSPLIT * HID_;

    float acc[8][8];
    #pragma unroll
    for (int i = 0; i < 8; ++i)
        #pragma unroll
        for (int j = 0; j < 8; ++j) acc[i][j] = 0.0f;

    const int m0 = blockIdx.x * BM;
    const int n0 = blockIdx.y * BN;
    sgemm_tile(A, G_ * FEAT_, W, HID_, KSPLIT, m0, n0, acc);

    float* P = g_part + (size_t)s * (2 * B_ * HID_);
    const int tx = threadIdx.x & 15, ty = threadIdx.x >> 4;
    #pragma unroll
    for (int i = 0; i < 8; ++i) {
        int row = m0 + ty * 8 + i;
        #pragma unroll
        for (int j = 0; j < 8; ++j) {
            int col = n0 + tx * 8 + j;
            P[(size_t)row * HID_ + col] = acc[i][j];
        }
    }
}

// reduce NSPLIT partials + bias + silu -> g_hg
__global__ __launch_bounds__(256) void k_reduce_silu(const float* __restrict__ bg1)
{
    int idx = blockIdx.x * blockDim.x + threadIdx.x;   // 0 .. 512*1024-1
    if (idx >= 2 * B_ * HID_) return;
    int col = idx & (HID_ - 1);
    float v = bg1[col];
    #pragma unroll
    for (int s = 0; s < NSPLIT; ++s)
        v += g_part[(size_t)s * (2 * B_ * HID_) + idx];
    g_hg[idx] = silu_f(v);
}

// ---------------- stage 4: global fc4 ----------------
// grid (4, 16)
__global__ __launch_bounds__(256) void k_global_fc4(
    const float* __restrict__ Wg4, const float* __restrict__ bg4)
{
    float acc[8][8];
    #pragma unroll
    for (int i = 0; i < 8; ++i)
        #pragma unroll
        for (int j = 0; j < 8; ++j) acc[i][j] = 0.0f;

    const int m0 = blockIdx.x * BM;
    const int n0 = blockIdx.y * BN;
    sgemm_tile(g_hg, HID_, Wg4, FEAT_, HID_, m0, n0, acc);

    const int tx = threadIdx.x & 15, ty = threadIdx.x >> 4;
    #pragma unroll
    for (int i = 0; i < 8; ++i) {
        int row = m0 + ty * 8 + i;
        #pragma unroll
        for (int j = 0; j < 8; ++j) {
            int col = n0 + tx * 8 + j;
            float v = acc[i][j] + bg4[col];
            g_o[(size_t)row * FEAT_ + col] = silu_f(v);
        }
    }
}

// ---------------- stage 5: per-batch dot ----------------
__global__ __launch_bounds__(256) void k_dot()
{
    const int b = blockIdx.x;
    const int t = threadIdx.x;
    const float* qo = g_o + (size_t)b * FEAT_;
    const float* ko = g_o + (size_t)(B_ + b) * FEAT_;
    float s = 0.0f;
    for (int i = t; i < FEAT_; i += 256)
        s = fmaf(qo[i], ko[i], s);
    __shared__ float sh[256];
    sh[t] = s;
    __syncthreads();
    for (int off = 128; off > 0; off >>= 1) {
        if (t < off) sh[t] += sh[t + off];
        __syncthreads();
    }
    if (t == 0) g_scores[b] = sh[0];
}

// ---------------- stage 6: softmax over batch ----------------
__global__ __launch_bounds__(256) void k_softmax(float* __restrict__ out)
{
    const int t = threadIdx.x;
    __shared__ float sh[256];
    float v = g_scores[t];
    sh[t] = v;
    __syncthreads();
    for (int off = 128; off > 0; off >>= 1) {
        if (t < off) sh[t] = fmaxf(sh[t], sh[t + off]);
        __syncthreads();
    }
    float m = sh[0];
    __syncthreads();
    float e = expf(v - m);
    sh[t] = e;
    __syncthreads();
    for (int off = 128; off > 0; off >>= 1) {
        if (t < off) sh[t] += sh[t + off];
        __syncthreads();
    }
    out[t] = e / sh[0];
}

// ---------------- launch ----------------
extern "C" void kernel_launch(void* const* d_in, const int* in_sizes, int n_in,
                              void* d_out, int out_size)
{
    const float* q   = (const float*)d_in[0];
    const float* k   = (const float*)d_in[1];
    const float* Wq1 = (const float*)d_in[2];
    const float* bq1 = (const float*)d_in[3];
    const float* Wq4 = (const float*)d_in[4];
    const float* bq4 = (const float*)d_in[5];
    const float* Wk1 = (const float*)d_in[6];
    const float* bk1 = (const float*)d_in[7];
    const float* Wk4 = (const float*)d_in[8];
    const float* bk4 = (const float*)d_in[9];
    const float* Wg1 = (const float*)d_in[10];
    const float* bg1 = (const float*)d_in[11];
    const float* Wg4 = (const float*)d_in[12];
    const float* bg4 = (const float*)d_in[13];
    float* out = (float*)d_out;

    k_grouped_fc1<<<dim3(B_ / BM, HID_ / BN, 2 * G_), 256>>>(q, k, Wq1, bq1, Wk1, bk1);
    k_grouped_fc4<<<dim3(B_ / BM, FEAT_ / BN, 2 * G_), 256>>>(Wq4, bq4, Wk4, bk4);
    k_global_fc1_splitk<<<dim3((2 * B_) / BM, HID_ / BN, NSPLIT), 256>>>(Wg1);
    k_reduce_silu<<<(2 * B_ * HID_) / 256, 256>>>(bg1);
    k_global_fc4<<<dim3((2 * B_) / BM, FEAT_ / BN, 1), 256>>>(Wg4, bg4);
    k_dot<<<B_, 256>>>();
    k_softmax<<<1, 256>>>(out);
}

// round 4
// speedup vs baseline: 2.5045x; 2.5045x over previous
#include <cuda_runtime.h>
#include <cuda_fp16.h>
#include <math.h>
#include <stdint.h>

#define B_    256
#define G_    16
#define GS_   588
#define HID_  1024
#define FEAT_ 2048
#define NSPL  8
#define KSPL  ((G_ * FEAT_) / NSPL)   // 4096

#define BM 128
#define BN 128
#define BK 32
#define BKP 40     // padded A row length in halves (80B rows -> conflict-free LDSM)
#define BNP 136    // padded B row length in halves (272B rows -> conflict-free LDSM)

// ---------------- scratch (device globals) ----------------
__device__ float g_h[(size_t)2 * B_ * G_ * HID_];        // [512][16384]
__device__ float g_f[(size_t)2 * B_ * G_ * FEAT_];       // [512][32768] interleaved o*16+g
__device__ float g_part[(size_t)NSPL * 2 * B_ * HID_];   // [8][512][1024]
__device__ float g_hg[(size_t)2 * B_ * HID_];            // [512][1024]
__device__ float g_o[(size_t)2 * B_ * FEAT_];            // [512][2048]
__device__ float g_scores[B_];

__device__ __forceinline__ float silu_f(float v) {
    return v / (1.0f + __expf(-v));
}

__device__ __forceinline__ uint32_t smem_to_u32(const void* p) {
    uint32_t a;
    asm("{ .reg .u64 t; cvta.to.shared.u64 t, %1; cvt.u32.u64 %0, t; }"
        : "=r"(a) : "l"(p));
    return a;
}

// ---- family-portable tensor-core primitives (valid on compute_103) ----
__device__ __forceinline__ void ldsm_x4(uint32_t* r, uint32_t addr) {
    asm volatile("ldmatrix.sync.aligned.m8n8.x4.shared.b16 {%0,%1,%2,%3}, [%4];"
        : "=r"(r[0]), "=r"(r[1]), "=r"(r[2]), "=r"(r[3]) : "r"(addr));
}
__device__ __forceinline__ void ldsm_x2t(uint32_t* r, uint32_t addr) {
    asm volatile("ldmatrix.sync.aligned.m8n8.x2.trans.shared.b16 {%0,%1}, [%2];"
        : "=r"(r[0]), "=r"(r[1]) : "r"(addr));
}
__device__ __forceinline__ void mma16816(float* d, const uint32_t* a, const uint32_t* b) {
    asm volatile(
        "mma.sync.aligned.m16n8k16.row.col.f32.f16.f16.f32 "
        "{%0,%1,%2,%3}, {%4,%5,%6,%7}, {%8,%9}, {%0,%1,%2,%3};"
        : "+f"(d[0]), "+f"(d[1]), "+f"(d[2]), "+f"(d[3])
        : "r"(a[0]), "r"(a[1]), "r"(a[2]), "r"(a[3]), "r"(b[0]), "r"(b[1]));
}

__device__ __forceinline__ void split_f32(float x, __half& hi, __half& lo) {
    hi = __float2half_rn(x);
    lo = __float2half_rn(x - __half2float(hi));
}

// ---------------- HMMA GEMM tile body ----------------
// acc[mt][nt][e] += A[m0..+127][0..K) * W[0..K)[n0..+127]  (fp32 in, fp32 out)
// A row-major [M,K] (lda), W row-major [K,N] (ldw). fp16 hi/lo 3-product split.
__device__ __forceinline__ void gemm_hmma(
    const float* __restrict__ A, int lda,
    const float* __restrict__ W, int ldw,
    int K, int m0, int n0, float acc[4][4][4])
{
    __shared__ __align__(128) __half sAhi[128 * BKP];
    __shared__ __align__(128) __half sAlo[128 * BKP];
    __shared__ __align__(128) __half sBhi[BK * BNP];
    __shared__ __align__(128) __half sBlo[BK * BNP];

    const int tid  = threadIdx.x;      // 256 threads
    const int lane = tid & 31;
    const int wid  = tid >> 5;
    const int wm   = (wid >> 2) * 64;  // warp grid 2(M) x 4(N)
    const int wn   = (wid & 3) * 32;

    const uint32_t aHiB = smem_to_u32(sAhi);
    const uint32_t aLoB = smem_to_u32(sAlo);
    const uint32_t bHiB = smem_to_u32(sBhi);
    const uint32_t bLoB = smem_to_u32(sBlo);

    #pragma unroll
    for (int mt = 0; mt < 4; ++mt)
        #pragma unroll
        for (int nt = 0; nt < 4; ++nt)
            #pragma unroll
            for (int e = 0; e < 4; ++e) acc[mt][nt][e] = 0.0f;

    // A loader: row = tid/2 (0..127), 16 consecutive k starting at (tid&1)*16
    const int ar  = tid >> 1;
    const int akb = (tid & 1) << 4;
    const float* Ap = A + (size_t)(m0 + ar) * lda;
    // B loader: k-row = tid/8 (0..31), 16 consecutive n starting at (tid&7)*16
    const int kr = tid >> 3;
    const int nb = (tid & 7) << 4;

    float ra[16], rb[16];
    const int nk = (K + BK - 1) / BK;

    auto load_tile = [&](int k0) {
        #pragma unroll
        for (int i = 0; i < 4; ++i) {
            const int kg = k0 + akb + i * 4;
            if (kg + 3 < K) {
                float4 v = *reinterpret_cast<const float4*>(Ap + kg);
                ra[i*4+0] = v.x; ra[i*4+1] = v.y; ra[i*4+2] = v.z; ra[i*4+3] = v.w;
            } else {
                #pragma unroll
                for (int j = 0; j < 4; ++j)
                    ra[i*4+j] = (kg + j < K) ? Ap[kg + j] : 0.0f;
            }
        }
        const int kgB = k0 + kr;
        const float* Wp = W + (size_t)kgB * ldw + n0 + nb;
        if (kgB < K) {
            #pragma unroll
            for (int i = 0; i < 4; ++i) {
                float4 v = *reinterpret_cast<const float4*>(Wp + i * 4);
                rb[i*4+0] = v.x; rb[i*4+1] = v.y; rb[i*4+2] = v.z; rb[i*4+3] = v.w;
            }
        } else {
            #pragma unroll
            for (int i = 0; i < 16; ++i) rb[i] = 0.0f;
        }
    };

    load_tile(0);

    for (int t = 0; t < nk; ++t) {
        // ---- convert + store staged regs to SMEM ----
        #pragma unroll
        for (int i = 0; i < 4; ++i) {
            const int kk = akb + i * 4;
            __half h0,l0,h1,l1,h2,l2,h3,l3;
            split_f32(ra[i*4+0], h0, l0); split_f32(ra[i*4+1], h1, l1);
            split_f32(ra[i*4+2], h2, l2); split_f32(ra[i*4+3], h3, l3);
            *reinterpret_cast<__half2*>(&sAhi[ar*BKP + kk])     = __halves2half2(h0, h1);
            *reinterpret_cast<__half2*>(&sAhi[ar*BKP + kk + 2]) = __halves2half2(h2, h3);
            *reinterpret_cast<__half2*>(&sAlo[ar*BKP + kk])     = __halves2half2(l0, l1);
            *reinterpret_cast<__half2*>(&sAlo[ar*BKP + kk + 2]) = __halves2half2(l2, l3);
        }
        #pragma unroll
        for (int i = 0; i < 4; ++i) {
            const int n = nb + i * 4;
            __half h0,l0,h1,l1,h2,l2,h3,l3;
            split_f32(rb[i*4+0], h0, l0); split_f32(rb[i*4+1], h1, l1);
            split_f32(rb[i*4+2], h2, l2); split_f32(rb[i*4+3], h3, l3);
            *reinterpret_cast<__half2*>(&sBhi[kr*BNP + n])     = __halves2half2(h0, h1);
            *reinterpret_cast<__half2*>(&sBhi[kr*BNP + n + 2]) = __halves2half2(h2, h3);
            *reinterpret_cast<__half2*>(&sBlo[kr*BNP + n])     = __halves2half2(l0, l1);
            *reinterpret_cast<__half2*>(&sBlo[kr*BNP + n + 2]) = __halves2half2(l2, l3);
        }
        __syncthreads();

        // prefetch next tile into regs (LDG latency hidden by MMAs below)
        if (t + 1 < nk) load_tile((t + 1) * BK);

        // ---- compute: 2 k16-steps ----
        #pragma unroll
        for (int ks = 0; ks < 2; ++ks) {
            const int l = lane & 15;
            uint32_t bh[4][2], bl[4][2];
            #pragma unroll
            for (int nt = 0; nt < 4; ++nt) {
                const uint32_t off =
                    ((uint32_t)(ks * 16 + l) * BNP + wn + nt * 8) * 2;
                ldsm_x2t(bh[nt], bHiB + off);
                ldsm_x2t(bl[nt], bLoB + off);
            }
            #pragma unroll
            for (int mt = 0; mt < 4; ++mt) {
                uint32_t ah[4], al[4];
                const uint32_t offa =
                    ((uint32_t)(wm + mt * 16 + l) * BKP + ks * 16 + (lane >> 4) * 8) * 2;
                ldsm_x4(ah, aHiB + offa);
                ldsm_x4(al, aLoB + offa);
                #pragma unroll
                for (int nt = 0; nt < 4; ++nt) {
                    mma16816(acc[mt][nt], ah, bh[nt]);  // hi*hi
                    mma16816(acc[mt][nt], ah, bl[nt]);  // hi*lo
                    mma16816(acc[mt][nt], al, bh[nt]);  // lo*hi
                }
            }
        }
        __syncthreads();
    }
}

// epilogue coordinate helper: element e of acc -> (row, col) offset
// e0:(r,c) e1:(r,c+1) e2:(r+8,c) e3:(r+8,c+1); r = base+lane/4, c = base+(lane%4)*2

// ================= stage kernels =================

// stage 1: grouped fc1.  grid (2, 8, 32): x=M-tile, y=N-tile, z=br*16+g
__global__ void __launch_bounds__(256, 1) k_fc1g(
    const float* __restrict__ q,  const float* __restrict__ k,
    const float* __restrict__ Wq1, const float* __restrict__ bq1,
    const float* __restrict__ Wk1, const float* __restrict__ bk1)
{
    const int z = blockIdx.z, br = z >> 4, g = z & 15;
    const int m0 = blockIdx.x * BM, n0 = blockIdx.y * BN;

    const float* A    = (br ? k : q) + g * GS_;
    const float* W    = (br ? Wk1 : Wq1) + (size_t)g * GS_ * HID_;
    const float* bias = (br ? bk1 : bq1) + g * HID_;

    float acc[4][4][4];
    gemm_hmma(A, G_ * GS_, W, HID_, GS_, m0, n0, acc);

    const int lane = threadIdx.x & 31, wid = threadIdx.x >> 5;
    const int wm = (wid >> 2) * 64, wn = (wid & 3) * 32;
    #pragma unroll
    for (int mt = 0; mt < 4; ++mt) {
        const int r = m0 + wm + mt * 16 + (lane >> 2);
        float* C0 = g_h + (size_t)(br * B_ + r)     * (G_ * HID_) + (size_t)g * HID_;
        float* C1 = g_h + (size_t)(br * B_ + r + 8) * (G_ * HID_) + (size_t)g * HID_;
        #pragma unroll
        for (int nt = 0; nt < 4; ++nt) {
            const int c = n0 + wn + nt * 8 + (lane & 3) * 2;
            const float b0 = bias[c], b1 = bias[c + 1];
            C0[c]     = silu_f(acc[mt][nt][0] + b0);
            C0[c + 1] = silu_f(acc[mt][nt][1] + b1);
            C1[c]     = silu_f(acc[mt][nt][2] + b0);
            C1[c + 1] = silu_f(acc[mt][nt][3] + b1);
        }
    }
}

// stage 2: grouped fc4 + feature-major interleave.  grid (2, 16, 32)
__global__ void __launch_bounds__(256, 1) k_fc4g(
    const float* __restrict__ Wq4, const float* __restrict__ bq4,
    const float* __restrict__ Wk4, const float* __restrict__ bk4)
{
    const int z = blockIdx.z, br = z >> 4, g = z & 15;
    const int m0 = blockIdx.x * BM, n0 = blockIdx.y * BN;

    const float* A    = g_h + (size_t)br * B_ * G_ * HID_ + (size_t)g * HID_;
    const float* W    = (br ? Wk4 : Wq4) + (size_t)g * HID_ * FEAT_;
    const float* bias = (br ? bk4 : bq4) + g * FEAT_;

    float acc[4][4][4];
    gemm_hmma(A, G_ * HID_, W, FEAT_, HID_, m0, n0, acc);

    const int lane = threadIdx.x & 31, wid = threadIdx.x >> 5;
    const int wm = (wid >> 2) * 64, wn = (wid & 3) * 32;
    #pragma unroll
    for (int mt = 0; mt < 4; ++mt) {
        const int r = m0 + wm + mt * 16 + (lane >> 2);
        float* C0 = g_f + (size_t)(br * B_ + r)     * (G_ * FEAT_) + g;
        float* C1 = g_f + (size_t)(br * B_ + r + 8) * (G_ * FEAT_) + g;
        #pragma unroll
        for (int nt = 0; nt < 4; ++nt) {
            const int c = n0 + wn + nt * 8 + (lane & 3) * 2;
            const float b0 = bias[c], b1 = bias[c + 1];
            C0[(size_t)c * G_]       = silu_f(acc[mt][nt][0] + b0);
            C0[(size_t)(c + 1) * G_] = silu_f(acc[mt][nt][1] + b1);
            C1[(size_t)c * G_]       = silu_f(acc[mt][nt][2] + b0);
            C1[(size_t)(c + 1) * G_] = silu_f(acc[mt][nt][3] + b1);
        }
    }
}

// stage 3: global fc1 split-K.  grid (4, 8, NSPL): M=512
__global__ void __launch_bounds__(256, 1) k_gf1(const float* __restrict__ Wg1)
{
    const int s = blockIdx.z;
    const int m0 = blockIdx.x * BM, n0 = blockIdx.y * BN;

    const float* A = g_f + (size_t)s * KSPL;
    const float* W = Wg1 + (size_t)s * KSPL * HID_;

    float acc[4][4][4];
    gemm_hmma(A, G_ * FEAT_, W, HID_, KSPL, m0, n0, acc);

    const int lane = threadIdx.x & 31, wid = threadIdx.x >> 5;
    const int wm = (wid >> 2) * 64, wn = (wid & 3) * 32;
    float* P = g_part + (size_t)s * (2 * B_ * HID_);
    #pragma unroll
    for (int mt = 0; mt < 4; ++mt) {
        const int r = m0 + wm + mt * 16 + (lane >> 2);
        #pragma unroll
        for (int nt = 0; nt < 4; ++nt) {
            const int c = n0 + wn + nt * 8 + (lane & 3) * 2;
            P[(size_t)r * HID_ + c]           = acc[mt][nt][0];
            P[(size_t)r * HID_ + c + 1]       = acc[mt][nt][1];
            P[(size_t)(r + 8) * HID_ + c]     = acc[mt][nt][2];
            P[(size_t)(r + 8) * HID_ + c + 1] = acc[mt][nt][3];
        }
    }
}

// reduce NSPL partials + bias + silu
__global__ void __launch_bounds__(256) k_reduce_silu(const float* __restrict__ bg1)
{
    const int idx = blockIdx.x * blockDim.x + threadIdx.x;
    if (idx >= 2 * B_ * HID_) return;
    const int col = idx & (HID_ - 1);
    float v = bg1[col];
    #pragma unroll
    for (int s = 0; s < NSPL; ++s)
        v += g_part[(size_t)s * (2 * B_ * HID_) + idx];
    g_hg[idx] = silu_f(v);
}

// stage 4: global fc4.  grid (4, 16)
__global__ void __launch_bounds__(256, 1) k_gf4(
    const float* __restrict__ Wg4, const float* __restrict__ bg4)
{
    const int m0 = blockIdx.x * BM, n0 = blockIdx.y * BN;

    float acc[4][4][4];
    gemm_hmma(g_hg, HID_, Wg4, FEAT_, HID_, m0, n0, acc);

    const int lane = threadIdx.x & 31, wid = threadIdx.x >> 5;
    const int wm = (wid >> 2) * 64, wn = (wid & 3) * 32;
    #pragma unroll
    for (int mt = 0; mt < 4; ++mt) {
        const int r = m0 + wm + mt * 16 + (lane >> 2);
        float* C0 = g_o + (size_t)r * FEAT_;
        float* C1 = g_o + (size_t)(r + 8) * FEAT_;
        #pragma unroll
        for (int nt = 0; nt < 4; ++nt) {
            const int c = n0 + wn + nt * 8 + (lane & 3) * 2;
            const float b0 = bg4[c], b1 = bg4[c + 1];
            C0[c]     = silu_f(acc[mt][nt][0] + b0);
            C0[c + 1] = silu_f(acc[mt][nt][1] + b1);
            C1[c]     = silu_f(acc[mt][nt][2] + b0);
            C1[c + 1] = silu_f(acc[mt][nt][3] + b1);
        }
    }
}

// stage 5: per-batch dot
__global__ void __launch_bounds__(256) k_dot()
{
    const int b = blockIdx.x;
    const int t = threadIdx.x;
    const float* qo = g_o + (size_t)b * FEAT_;
    const float* ko = g_o + (size_t)(B_ + b) * FEAT_;
    float s = 0.0f;
    for (int i = t; i < FEAT_; i += 256)
        s = fmaf(qo[i], ko[i], s);
    __shared__ float sh[256];
    sh[t] = s;
    __syncthreads();
    for (int off = 128; off > 0; off >>= 1) {
        if (t < off) sh[t] += sh[t + off];
        __syncthreads();
    }
    if (t == 0) g_scores[b] = sh[0];
}

// stage 6: softmax over batch
__global__ void __launch_bounds__(256) k_softmax(float* __restrict__ out)
{
    const int t = threadIdx.x;
    __shared__ float sh[256];
    float v = g_scores[t];
    sh[t] = v;
    __syncthreads();
    for (int off = 128; off > 0; off >>= 1) {
        if (t < off) sh[t] = fmaxf(sh[t], sh[t + off]);
        __syncthreads();
    }
    const float m = sh[0];
    __syncthreads();
    const float e = expf(v - m);
    sh[t] = e;
    __syncthreads();
    for (int off = 128; off > 0; off >>= 1) {
        if (t < off) sh[t] += sh[t + off];
        __syncthreads();
    }
    out[t] = e / sh[0];
}

// ================= launch =================
extern "C" void kernel_launch(void* const* d_in, const int* in_sizes, int n_in,
                              void* d_out, int out_size)
{
    const float* q   = (const float*)d_in[0];
    const float* k   = (const float*)d_in[1];
    const float* Wq1 = (const float*)d_in[2];
    const float* bq1 = (const float*)d_in[3];
    const float* Wq4 = (const float*)d_in[4];
    const float* bq4 = (const float*)d_in[5];
    const float* Wk1 = (const float*)d_in[6];
    const float* bk1 = (const float*)d_in[7];
    const float* Wk4 = (const float*)d_in[8];
    const float* bk4 = (const float*)d_in[9];
    const float* Wg1 = (const float*)d_in[10];
    const float* bg1 = (const float*)d_in[11];
    const float* Wg4 = (const float*)d_in[12];
    const float* bg4 = (const float*)d_in[13];
    float* out = (float*)d_out;

    k_fc1g<<<dim3(2, 8, 2 * G_),  256>>>(q, k, Wq1, bq1, Wk1, bk1);
    k_fc4g<<<dim3(2, 16, 2 * G_), 256>>>(Wq4, bq4, Wk4, bk4);
    k_gf1<<<dim3(4, 8, NSPL),     256>>>(Wg1);
    k_reduce_silu<<<(2 * B_ * HID_) / 256, 256>>>(bg1);
    k_gf4<<<dim3(4, 16, 1),       256>>>(Wg4, bg4);
    k_dot<<<B_, 256>>>();
    k_softmax<<<1, 256>>>(out);
}

// round 5
// speedup vs baseline: 2.5141x; 1.0038x over previous
#include <cuda_runtime.h>
#include <cuda_fp16.h>
#include <math.h>
#include <stdint.h>

#define B_    256
#define G_    16
#define GS_   588
#define HID_  1024
#define FEAT_ 2048
#define NSPL  8
#define KSPL  ((G_ * FEAT_) / NSPL)   // 4096

#define BM 128
#define BN 128
#define BK 32
#define BKP 40     // padded A row (halves)
#define BNP 136    // padded B row (halves)

// per-buffer SMEM layout (bytes)
#define PB_AHI 0
#define PB_ALO 10240
#define PB_BHI 20480
#define PB_BLO 29184
#define BUF_BYTES 37888
#define SMEM_TOTAL (2 * BUF_BYTES)   // 75776

// ---------------- scratch (device globals) ----------------
__device__ __half g_h_hi[(size_t)2 * B_ * G_ * HID_];
__device__ __half g_h_lo[(size_t)2 * B_ * G_ * HID_];
__device__ __half g_f_hi[(size_t)2 * B_ * G_ * FEAT_];
__device__ __half g_f_lo[(size_t)2 * B_ * G_ * FEAT_];
__device__ float  g_part[(size_t)NSPL * 2 * B_ * HID_];
__device__ __half g_hg_hi[(size_t)2 * B_ * HID_];
__device__ __half g_hg_lo[(size_t)2 * B_ * HID_];
__device__ float  g_o[(size_t)2 * B_ * FEAT_];
__device__ float  g_scores[B_];

__device__ __forceinline__ float silu_f(float v) {
    return v / (1.0f + __expf(-v));
}
__device__ __forceinline__ uint32_t smem_to_u32(const void* p) {
    uint32_t a;
    asm("{ .reg .u64 t; cvta.to.shared.u64 t, %1; cvt.u32.u64 %0, t; }"
        : "=r"(a) : "l"(p));
    return a;
}

// ---- family-portable primitives (valid on compute_103) ----
__device__ __forceinline__ void ldsm_x4(uint32_t* r, uint32_t addr) {
    asm volatile("ldmatrix.sync.aligned.m8n8.x4.shared.b16 {%0,%1,%2,%3}, [%4];"
        : "=r"(r[0]), "=r"(r[1]), "=r"(r[2]), "=r"(r[3]) : "r"(addr));
}
__device__ __forceinline__ void ldsm_x2t(uint32_t* r, uint32_t addr) {
    asm volatile("ldmatrix.sync.aligned.m8n8.x2.trans.shared.b16 {%0,%1}, [%2];"
        : "=r"(r[0]), "=r"(r[1]) : "r"(addr));
}
__device__ __forceinline__ void mma_f32(float* d, const uint32_t* a, const uint32_t* b) {
    asm volatile(
        "mma.sync.aligned.m16n8k16.row.col.f32.f16.f16.f32 "
        "{%0,%1,%2,%3}, {%4,%5,%6,%7}, {%8,%9}, {%0,%1,%2,%3};"
        : "+f"(d[0]), "+f"(d[1]), "+f"(d[2]), "+f"(d[3])
        : "r"(a[0]), "r"(a[1]), "r"(a[2]), "r"(a[3]), "r"(b[0]), "r"(b[1]));
}
__device__ __forceinline__ void mma_f16(uint32_t* d, const uint32_t* a, const uint32_t* b) {
    asm volatile(
        "mma.sync.aligned.m16n8k16.row.col.f16.f16.f16.f16 "
        "{%0,%1}, {%2,%3,%4,%5}, {%6,%7}, {%0,%1};"
        : "+r"(d[0]), "+r"(d[1])
        : "r"(a[0]), "r"(a[1]), "r"(a[2]), "r"(a[3]), "r"(b[0]), "r"(b[1]));
}
__device__ __forceinline__ void cp_async16(uint32_t dst, const void* src) {
    asm volatile("cp.async.ca.shared.global [%0], [%1], 16;" :: "r"(dst), "l"(src));
}
__device__ __forceinline__ void cp_async_commit() {
    asm volatile("cp.async.commit_group;" ::: "memory");
}
__device__ __forceinline__ void cp_async_wait0() {
    asm volatile("cp.async.wait_group 0;" ::: "memory");
}

__device__ __forceinline__ void split_f32(float x, __half& hi, __half& lo) {
    hi = __float2half_rn(x);
    lo = __float2half_rn(x - __half2float(hi));
}
__device__ __forceinline__ void split_store2(__half* hi, __half* lo, float v0, float v1) {
    __half h0, l0, h1, l1;
    split_f32(v0, h0, l0); split_f32(v1, h1, l1);
    *reinterpret_cast<__half2*>(hi) = __halves2half2(h0, h1);
    *reinterpret_cast<__half2*>(lo) = __halves2half2(l0, l1);
}

// ---------------- GEMM body ----------------
// acc[mt][nt][e] = A[m0..+127][0..K) * W[0..K)[n0..+127], fp32 result.
// AF16: A given as pre-split hi/lo half arrays (K%32==0 assumed).
// else: A fp32 with tail predication.
template<bool AF16>
__device__ __forceinline__ void gemm_body(
    const float* __restrict__ Af,
    const __half* __restrict__ Ah, const __half* __restrict__ Al, int lda,
    const float* __restrict__ W, int ldw,
    int K, int m0, int n0, float acc[4][4][4])
{
    extern __shared__ char dyn[];
    const uint32_t sb = smem_to_u32(dyn);

    const int tid  = threadIdx.x;
    const int lane = tid & 31;
    const int wid  = tid >> 5;
    const int wm   = (wid >> 2) * 64;
    const int wn   = (wid & 3) * 32;

    // A loader: row = tid/2, 16 halves/floats from (tid&1)*16
    const int ar  = tid >> 1;
    const int akb = (tid & 1) << 4;
    // B loader: k-row = tid/8, 16 floats from (tid&7)*16
    const int kr = tid >> 3;
    const int nb = (tid & 7) << 4;

    const int nk = (K + BK - 1) / BK;

    uint32_t accc[4][4][2];
    #pragma unroll
    for (int mt = 0; mt < 4; ++mt)
        #pragma unroll
        for (int nt = 0; nt < 4; ++nt) {
            accc[mt][nt][0] = 0u; accc[mt][nt][1] = 0u;
            #pragma unroll
            for (int e = 0; e < 4; ++e) acc[mt][nt][e] = 0.0f;
        }

    float ra[16], rb[16];
    const float* Apf = AF16 ? nullptr : (Af + (size_t)(m0 + ar) * lda);

    auto ldgA_f32 = [&](int k0) {
        #pragma unroll
        for (int i = 0; i < 4; ++i) {
            const int kg = k0 + akb + i * 4;
            if (kg + 3 < K) {
                float4 v = *reinterpret_cast<const float4*>(Apf + kg);
                ra[i*4+0] = v.x; ra[i*4+1] = v.y; ra[i*4+2] = v.z; ra[i*4+3] = v.w;
            } else {
                #pragma unroll
                for (int j = 0; j < 4; ++j)
                    ra[i*4+j] = (kg + j < K) ? Apf[kg + j] : 0.0f;
            }
        }
    };
    auto cpA_f16 = [&](int k0, int buf) {
        const uint32_t d = sb + buf * BUF_BYTES + (uint32_t)(ar * BKP + akb) * 2;
        const size_t go = (size_t)(m0 + ar) * lda + k0 + akb;
        cp_async16(d + PB_AHI,      Ah + go);
        cp_async16(d + PB_AHI + 16, Ah + go + 8);
        cp_async16(d + PB_ALO,      Al + go);
        cp_async16(d + PB_ALO + 16, Al + go + 8);
    };
    auto ldgB = [&](int k0) {
        const int kgB = k0 + kr;
        if (kgB < K) {
            const float* Wp = W + (size_t)kgB * ldw + n0 + nb;
            #pragma unroll
            for (int i = 0; i < 4; ++i) {
                float4 v = *reinterpret_cast<const float4*>(Wp + i * 4);
                rb[i*4+0] = v.x; rb[i*4+1] = v.y; rb[i*4+2] = v.z; rb[i*4+3] = v.w;
            }
        } else {
            #pragma unroll
            for (int i = 0; i < 16; ++i) rb[i] = 0.0f;
        }
    };
    auto stA_f32 = [&](int buf) {
        __half* sAhi = reinterpret_cast<__half*>(dyn + buf * BUF_BYTES + PB_AHI);
        __half* sAlo = reinterpret_cast<__half*>(dyn + buf * BUF_BYTES + PB_ALO);
        #pragma unroll
        for (int i = 0; i < 4; ++i) {
            const int kk = akb + i * 4;
            __half h0,l0,h1,l1,h2,l2,h3,l3;
            split_f32(ra[i*4+0], h0, l0); split_f32(ra[i*4+1], h1, l1);
            split_f32(ra[i*4+2], h2, l2); split_f32(ra[i*4+3], h3, l3);
            *reinterpret_cast<__half2*>(&sAhi[ar*BKP + kk])     = __halves2half2(h0, h1);
            *reinterpret_cast<__half2*>(&sAhi[ar*BKP + kk + 2]) = __halves2half2(h2, h3);
            *reinterpret_cast<__half2*>(&sAlo[ar*BKP + kk])     = __halves2half2(l0, l1);
            *reinterpret_cast<__half2*>(&sAlo[ar*BKP + kk + 2]) = __halves2half2(l2, l3);
        }
    };
    auto stB = [&](int buf) {
        __half* sBhi = reinterpret_cast<__half*>(dyn + buf * BUF_BYTES + PB_BHI);
        __half* sBlo = reinterpret_cast<__half*>(dyn + buf * BUF_BYTES + PB_BLO);
        #pragma unroll
        for (int i = 0; i < 4; ++i) {
            const int n = nb + i * 4;
            __half h0,l0,h1,l1,h2,l2,h3,l3;
            split_f32(rb[i*4+0], h0, l0); split_f32(rb[i*4+1], h1, l1);
            split_f32(rb[i*4+2], h2, l2); split_f32(rb[i*4+3], h3, l3);
            *reinterpret_cast<__half2*>(&sBhi[kr*BNP + n])     = __halves2half2(h0, h1);
            *reinterpret_cast<__half2*>(&sBhi[kr*BNP + n + 2]) = __halves2half2(h2, h3);
            *reinterpret_cast<__half2*>(&sBlo[kr*BNP + n])     = __halves2half2(l0, l1);
            *reinterpret_cast<__half2*>(&sBlo[kr*BNP + n + 2]) = __halves2half2(l2, l3);
        }
    };

    // prologue: stage tile 0 into buf 0
    if (AF16) cpA_f16(0, 0); else { ldgA_f32(0); }
    ldgB(0);
    if (!AF16) stA_f32(0);
    stB(0);
    if (AF16) { cp_async_commit(); cp_async_wait0(); }
    __syncthreads();

    for (int t = 0; t < nk; ++t) {
        const int cur = t & 1, nxt = (t + 1) & 1;
        const bool more = (t + 1) < nk;

        // 1) issue next tile's loads (LDG/cp.async; no dependents yet)
        if (more) {
            if (AF16) { cpA_f16((t + 1) * BK, nxt); cp_async_commit(); }
            else      { ldgA_f32((t + 1) * BK); }
            ldgB((t + 1) * BK);
        }

        // 2) MMA on current buffer (hides load latency)
        {
            const uint32_t aHiB = sb + cur * BUF_BYTES + PB_AHI;
            const uint32_t aLoB = sb + cur * BUF_BYTES + PB_ALO;
            const uint32_t bHiB = sb + cur * BUF_BYTES + PB_BHI;
            const uint32_t bLoB = sb + cur * BUF_BYTES + PB_BLO;
            const int l = lane & 15;
            #pragma unroll
            for (int ks = 0; ks < 2; ++ks) {
                uint32_t bh[4][2], bl[4][2];
                #pragma unroll
                for (int nt = 0; nt < 4; ++nt) {
                    const uint32_t off =
                        ((uint32_t)(ks * 16 + l) * BNP + wn + nt * 8) * 2;
                    ldsm_x2t(bh[nt], bHiB + off);
                    ldsm_x2t(bl[nt], bLoB + off);
                }
                #pragma unroll
                for (int mt = 0; mt < 4; ++mt) {
                    uint32_t ah[4], al[4];
                    const uint32_t offa =
                        ((uint32_t)(wm + mt * 16 + l) * BKP + ks * 16 + (lane >> 4) * 8) * 2;
                    ldsm_x4(ah, aHiB + offa);
                    ldsm_x4(al, aLoB + offa);
                    #pragma unroll
                    for (int nt = 0; nt < 4; ++nt) {
                        mma_f32(acc[mt][nt], ah, bh[nt]);      // hi*hi  (f32 acc)
                        mma_f16(accc[mt][nt], ah, bl[nt]);     // hi*lo  (f16 acc)
                        mma_f16(accc[mt][nt], al, bh[nt]);     // lo*hi  (f16 acc)
                    }
                }
            }
        }

        // 3) convert+store next tile (in MMA shadow), then publish
        if (more) {
            if (!AF16) stA_f32(nxt);
            stB(nxt);
            if (AF16) cp_async_wait0();
        }
        __syncthreads();
    }

    // merge fp16 correction accumulators into fp32 accs
    #pragma unroll
    for (int mt = 0; mt < 4; ++mt)
        #pragma unroll
        for (int nt = 0; nt < 4; ++nt) {
            const __half2 c01 = *reinterpret_cast<const __half2*>(&accc[mt][nt][0]);
            const __half2 c23 = *reinterpret_cast<const __half2*>(&accc[mt][nt][1]);
            acc[mt][nt][0] += __low2float(c01);
            acc[mt][nt][1] += __high2float(c01);
            acc[mt][nt][2] += __low2float(c23);
            acc[mt][nt][3] += __high2float(c23);
        }
}

// ================= stage kernels =================

// stage 1: grouped fc1 (A fp32). grid (2, 8, 32)
__global__ void __launch_bounds__(256, 1) k_fc1g(
    const float* __restrict__ q,  const float* __restrict__ k,
    const float* __restrict__ Wq1, const float* __restrict__ bq1,
    const float* __restrict__ Wk1, const float* __restrict__ bk1)
{
    const int z = blockIdx.z, br = z >> 4, g = z & 15;
    const int m0 = blockIdx.x * BM, n0 = blockIdx.y * BN;

    const float* A    = (br ? k : q) + g * GS_;
    const float* W    = (br ? Wk1 : Wq1) + (size_t)g * GS_ * HID_;
    const float* bias = (br ? bk1 : bq1) + g * HID_;

    float acc[4][4][4];
    gemm_body<false>(A, nullptr, nullptr, G_ * GS_, W, HID_, GS_, m0, n0, acc);

    const int lane = threadIdx.x & 31, wid = threadIdx.x >> 5;
    const int wm = (wid >> 2) * 64, wn = (wid & 3) * 32;
    #pragma unroll
    for (int mt = 0; mt < 4; ++mt) {
        const int r = m0 + wm + mt * 16 + (lane >> 2);
        #pragma unroll
        for (int nt = 0; nt < 4; ++nt) {
            const int c = n0 + wn + nt * 8 + (lane & 3) * 2;
            const float b0 = bias[c], b1 = bias[c + 1];
            const size_t i0 = (size_t)(br * B_ + r) * (G_ * HID_) + (size_t)g * HID_ + c;
            const size_t i1 = i0 + (size_t)8 * (G_ * HID_);
            split_store2(&g_h_hi[i0], &g_h_lo[i0],
                         silu_f(acc[mt][nt][0] + b0), silu_f(acc[mt][nt][1] + b1));
            split_store2(&g_h_hi[i1], &g_h_lo[i1],
                         silu_f(acc[mt][nt][2] + b0), silu_f(acc[mt][nt][3] + b1));
        }
    }
}

// stage 2: grouped fc4 + feature-major interleave (A pre-split). grid (2, 16, 32)
__global__ void __launch_bounds__(256, 1) k_fc4g(
    const float* __restrict__ Wq4, const float* __restrict__ bq4,
    const float* __restrict__ Wk4, const float* __restrict__ bk4)
{
    const int z = blockIdx.z, br = z >> 4, g = z & 15;
    const int m0 = blockIdx.x * BM, n0 = blockIdx.y * BN;

    const __half* Ah  = g_h_hi + (size_t)br * B_ * G_ * HID_ + (size_t)g * HID_;
    const __half* Al  = g_h_lo + (size_t)br * B_ * G_ * HID_ + (size_t)g * HID_;
    const float* W    = (br ? Wk4 : Wq4) + (size_t)g * HID_ * FEAT_;
    const float* bias = (br ? bk4 : bq4) + g * FEAT_;

    float acc[4][4][4];
    gemm_body<true>(nullptr, Ah, Al, G_ * HID_, W, FEAT_, HID_, m0, n0, acc);

    const int lane = threadIdx.x & 31, wid = threadIdx.x >> 5;
    const int wm = (wid >> 2) * 64, wn = (wid & 3) * 32;
    #pragma unroll
    for (int mt = 0; mt < 4; ++mt) {
        const int r = m0 + wm + mt * 16 + (lane >> 2);
        const size_t rb0 = (size_t)(br * B_ + r)     * (G_ * FEAT_) + g;
        const size_t rb1 = (size_t)(br * B_ + r + 8) * (G_ * FEAT_) + g;
        #pragma unroll
        for (int nt = 0; nt < 4; ++nt) {
            const int c = n0 + wn + nt * 8 + (lane & 3) * 2;
            const float b0 = bias[c], b1 = bias[c + 1];
            const float v0 = silu_f(acc[mt][nt][0] + b0);
            const float v1 = silu_f(acc[mt][nt][1] + b1);
            const float v2 = silu_f(acc[mt][nt][2] + b0);
            const float v3 = silu_f(acc[mt][nt][3] + b1);
            __half h, l;
            split_f32(v0, h, l); g_f_hi[rb0 + (size_t)c * G_] = h;       g_f_lo[rb0 + (size_t)c * G_] = l;
            split_f32(v1, h, l); g_f_hi[rb0 + (size_t)(c + 1) * G_] = h; g_f_lo[rb0 + (size_t)(c + 1) * G_] = l;
            split_f32(v2, h, l); g_f_hi[rb1 + (size_t)c * G_] = h;       g_f_lo[rb1 + (size_t)c * G_] = l;
            split_f32(v3, h, l); g_f_hi[rb1 + (size_t)(c + 1) * G_] = h; g_f_lo[rb1 + (size_t)(c + 1) * G_] = l;
        }
    }
}

// stage 3: global fc1 split-K (A pre-split). grid (4, 8, NSPL)
__global__ void __launch_bounds__(256, 1) k_gf1(const float* __restrict__ Wg1)
{
    const int s = blockIdx.z;
    const int m0 = blockIdx.x * BM, n0 = blockIdx.y * BN;

    const __half* Ah = g_f_hi + (size_t)s * KSPL;
    const __half* Al = g_f_lo + (size_t)s * KSPL;
    const float*  W  = Wg1 + (size_t)s * KSPL * HID_;

    float acc[4][4][4];
    gemm_body<true>(nullptr, Ah, Al, G_ * FEAT_, W, HID_, KSPL, m0, n0, acc);

    const int lane = threadIdx.x & 31, wid = threadIdx.x >> 5;
    const int wm = (wid >> 2) * 64, wn = (wid & 3) * 32;
    float* P = g_part + (size_t)s * (2 * B_ * HID_);
    #pragma unroll
    for (int mt = 0; mt < 4; ++mt) {
        const int r = m0 + wm + mt * 16 + (lane >> 2);
        #pragma unroll
        for (int nt = 0; nt < 4; ++nt) {
            const int c = n0 + wn + nt * 8 + (lane & 3) * 2;
            P[(size_t)r * HID_ + c]           = acc[mt][nt][0];
            P[(size_t)r * HID_ + c + 1]       = acc[mt][nt][1];
            P[(size_t)(r + 8) * HID_ + c]     = acc[mt][nt][2];
            P[(size_t)(r + 8) * HID_ + c + 1] = acc[mt][nt][3];
        }
    }
}

// reduce NSPL partials + bias + silu -> pre-split g_hg
__global__ void __launch_bounds__(256) k_reduce_silu(const float* __restrict__ bg1)
{
    const int idx = blockIdx.x * blockDim.x + threadIdx.x;
    if (idx >= 2 * B_ * HID_) return;
    const int col = idx & (HID_ - 1);
    float v = bg1[col];
    #pragma unroll
    for (int s = 0; s < NSPL; ++s)
        v += g_part[(size_t)s * (2 * B_ * HID_) + idx];
    v = silu_f(v);
    __half h, l;
    split_f32(v, h, l);
    g_hg_hi[idx] = h;
    g_hg_lo[idx] = l;
}

// stage 4: global fc4 (A pre-split). grid (4, 16)
__global__ void __launch_bounds__(256, 1) k_gf4(
    const float* __restrict__ Wg4, const float* __restrict__ bg4)
{
    const int m0 = blockIdx.x * BM, n0 = blockIdx.y * BN;

    float acc[4][4][4];
    gemm_body<true>(nullptr, g_hg_hi, g_hg_lo, HID_, Wg4, FEAT_, HID_, m0, n0, acc);

    const int lane = threadIdx.x & 31, wid = threadIdx.x >> 5;
    const int wm = (wid >> 2) * 64, wn = (wid & 3) * 32;
    #pragma unroll
    for (int mt = 0; mt < 4; ++mt) {
        const int r = m0 + wm + mt * 16 + (lane >> 2);
        float* C0 = g_o + (size_t)r * FEAT_;
        float* C1 = g_o + (size_t)(r + 8) * FEAT_;
        #pragma unroll
        for (int nt = 0; nt < 4; ++nt) {
            const int c = n0 + wn + nt * 8 + (lane & 3) * 2;
            const float b0 = bg4[c], b1 = bg4[c + 1];
            C0[c]     = silu_f(acc[mt][nt][0] + b0);
            C0[c + 1] = silu_f(acc[mt][nt][1] + b1);
            C1[c]     = silu_f(acc[mt][nt][2] + b0);
            C1[c + 1] = silu_f(acc[mt][nt][3] + b1);
        }
    }
}

// stage 5: per-batch dot
__global__ void __launch_bounds__(256) k_dot()
{
    const int b = blockIdx.x;
    const int t = threadIdx.x;
    const float* qo = g_o + (size_t)b * FEAT_;
    const float* ko = g_o + (size_t)(B_ + b) * FEAT_;
    float s = 0.0f;
    for (int i = t; i < FEAT_; i += 256)
        s = fmaf(qo[i], ko[i], s);
    __shared__ float sh[256];
    sh[t] = s;
    __syncthreads();
    for (int off = 128; off > 0; off >>= 1) {
        if (t < off) sh[t] += sh[t + off];
        __syncthreads();
    }
    if (t == 0) g_scores[b] = sh[0];
}

// stage 6: softmax over batch
__global__ void __launch_bounds__(256) k_softmax(float* __restrict__ out)
{
    const int t = threadIdx.x;
    __shared__ float sh[256];
    float v = g_scores[t];
    sh[t] = v;
    __syncthreads();
    for (int off = 128; off > 0; off >>= 1) {
        if (t < off) sh[t] = fmaxf(sh[t], sh[t + off]);
        __syncthreads();
    }
    const float m = sh[0];
    __syncthreads();
    const float e = expf(v - m);
    sh[t] = e;
    __syncthreads();
    for (int off = 128; off > 0; off >>= 1) {
        if (t < off) sh[t] += sh[t + off];
        __syncthreads();
    }
    out[t] = e / sh[0];
}

// ================= launch =================
extern "C" void kernel_launch(void* const* d_in, const int* in_sizes, int n_in,
                              void* d_out, int out_size)
{
    const float* q   = (const float*)d_in[0];
    const float* k   = (const float*)d_in[1];
    const float* Wq1 = (const float*)d_in[2];
    const float* bq1 = (const float*)d_in[3];
    const float* Wq4 = (const float*)d_in[4];
    const float* bq4 = (const float*)d_in[5];
    const float* Wk1 = (const float*)d_in[6];
    const float* bk1 = (const float*)d_in[7];
    const float* Wk4 = (const float*)d_in[8];
    const float* bk4 = (const float*)d_in[9];
    const float* Wg1 = (const float*)d_in[10];
    const float* bg1 = (const float*)d_in[11];
    const float* Wg4 = (const float*)d_in[12];
    const float* bg4 = (const float*)d_in[13];
    float* out = (float*)d_out;

    static int attr_done = 0;
    // setting a func attribute is idempotent and not a stream op; do it every call
    cudaFuncSetAttribute(k_fc1g, cudaFuncAttributeMaxDynamicSharedMemorySize, SMEM_TOTAL);
    cudaFuncSetAttribute(k_fc4g, cudaFuncAttributeMaxDynamicSharedMemorySize, SMEM_TOTAL);
    cudaFuncSetAttribute(k_gf1,  cudaFuncAttributeMaxDynamicSharedMemorySize, SMEM_TOTAL);
    cudaFuncSetAttribute(k_gf4,  cudaFuncAttributeMaxDynamicSharedMemorySize, SMEM_TOTAL);
    (void)attr_done;

    k_fc1g<<<dim3(2, 8, 2 * G_),  256, SMEM_TOTAL>>>(q, k, Wq1, bq1, Wk1, bk1);
    k_fc4g<<<dim3(2, 16, 2 * G_), 256, SMEM_TOTAL>>>(Wq4, bq4, Wk4, bk4);
    k_gf1<<<dim3(4, 8, NSPL),     256, SMEM_TOTAL>>>(Wg1);
    k_reduce_silu<<<(2 * B_ * HID_) / 256, 256>>>(bg1);
    k_gf4<<<dim3(4, 16, 1),       256, SMEM_TOTAL>>>(Wg4, bg4);
    k_dot<<<B_, 256>>>();
    k_softmax<<<1, 256>>>(out);
}

// round 6
// speedup vs baseline: 2.5387x; 1.0098x over previous
#include <cuda_runtime.h>
#include <cuda_fp16.h>
#include <math.h>
#include <stdint.h>

#define B_    256
#define G_    16
#define GS_   588
#define HID_  1024
#define FEAT_ 2048
#define NSPL  8
#define KSPL  ((G_ * FEAT_) / NSPL)   // 4096

#define THREADS 512
#define BM 128
#define BN 128
#define BK 32
#define BKP 40     // padded A row (halves)
#define BNP 136    // padded B row (halves)

// per-buffer SMEM layout (bytes)
#define PB_AHI 0
#define PB_ALO 10240
#define PB_BHI 20480
#define PB_BLO 29184
#define BUF_BYTES 37888
#define SMEM_TOTAL (2 * BUF_BYTES)   // 75776

// ---------------- scratch (device globals) ----------------
__device__ __half g_h_hi[(size_t)2 * B_ * G_ * HID_];
__device__ __half g_h_lo[(size_t)2 * B_ * G_ * HID_];
__device__ __half g_f_hi[(size_t)2 * B_ * G_ * FEAT_];
__device__ __half g_f_lo[(size_t)2 * B_ * G_ * FEAT_];
__device__ float  g_part[(size_t)NSPL * 2 * B_ * HID_];
__device__ __half g_hg_hi[(size_t)2 * B_ * HID_];
__device__ __half g_hg_lo[(size_t)2 * B_ * HID_];
__device__ float  g_o[(size_t)2 * B_ * FEAT_];
__device__ float  g_scores[B_];

__device__ __forceinline__ float silu_f(float v) {
    return v / (1.0f + __expf(-v));
}
__device__ __forceinline__ uint32_t smem_to_u32(const void* p) {
    uint32_t a;
    asm("{ .reg .u64 t; cvta.to.shared.u64 t, %1; cvt.u32.u64 %0, t; }"
        : "=r"(a) : "l"(p));
    return a;
}

// ---- family-portable primitives (valid on compute_103) ----
__device__ __forceinline__ void ldsm_x4(uint32_t* r, uint32_t addr) {
    asm volatile("ldmatrix.sync.aligned.m8n8.x4.shared.b16 {%0,%1,%2,%3}, [%4];"
        : "=r"(r[0]), "=r"(r[1]), "=r"(r[2]), "=r"(r[3]) : "r"(addr));
}
__device__ __forceinline__ void ldsm_x2t(uint32_t* r, uint32_t addr) {
    asm volatile("ldmatrix.sync.aligned.m8n8.x2.trans.shared.b16 {%0,%1}, [%2];"
        : "=r"(r[0]), "=r"(r[1]) : "r"(addr));
}
__device__ __forceinline__ void mma_f32(float* d, const uint32_t* a, const uint32_t* b) {
    asm volatile(
        "mma.sync.aligned.m16n8k16.row.col.f32.f16.f16.f32 "
        "{%0,%1,%2,%3}, {%4,%5,%6,%7}, {%8,%9}, {%0,%1,%2,%3};"
        : "+f"(d[0]), "+f"(d[1]), "+f"(d[2]), "+f"(d[3])
        : "r"(a[0]), "r"(a[1]), "r"(a[2]), "r"(a[3]), "r"(b[0]), "r"(b[1]));
}
__device__ __forceinline__ void mma_f16(uint32_t* d, const uint32_t* a, const uint32_t* b) {
    asm volatile(
        "mma.sync.aligned.m16n8k16.row.col.f16.f16.f16.f16 "
        "{%0,%1}, {%2,%3,%4,%5}, {%6,%7}, {%0,%1};"
        : "+r"(d[0]), "+r"(d[1])
        : "r"(a[0]), "r"(a[1]), "r"(a[2]), "r"(a[3]), "r"(b[0]), "r"(b[1]));
}
__device__ __forceinline__ void cp_async16(uint32_t dst, const void* src) {
    asm volatile("cp.async.ca.shared.global [%0], [%1], 16;" :: "r"(dst), "l"(src));
}
__device__ __forceinline__ void cp_async_commit() {
    asm volatile("cp.async.commit_group;" ::: "memory");
}
__device__ __forceinline__ void cp_async_wait0() {
    asm volatile("cp.async.wait_group 0;" ::: "memory");
}

__device__ __forceinline__ void split_f32(float x, __half& hi, __half& lo) {
    hi = __float2half_rn(x);
    lo = __float2half_rn(x - __half2float(hi));
}
__device__ __forceinline__ void split_store2(__half* hi, __half* lo, float v0, float v1) {
    __half h0, l0, h1, l1;
    split_f32(v0, h0, l0); split_f32(v1, h1, l1);
    *reinterpret_cast<__half2*>(hi) = __halves2half2(h0, h1);
    *reinterpret_cast<__half2*>(lo) = __halves2half2(l0, l1);
}

// ---------------- GEMM body (512 threads, warp grid 4x4, 32x32/warp) ----------
// acc[mt][nt][e] = A[m0..+127][0..K) * W[0..K)[n0..+127]
// AF16: A pre-split hi/lo halves (K%32==0). else A fp32 with tail predication.
template<bool AF16>
__device__ __forceinline__ void gemm_body(
    const float* __restrict__ Af,
    const __half* __restrict__ Ah, const __half* __restrict__ Al, int lda,
    const float* __restrict__ W, int ldw,
    int K, int m0, int n0, float acc[2][4][4])
{
    extern __shared__ char dyn[];
    const uint32_t sb = smem_to_u32(dyn);

    const int tid  = threadIdx.x;
    const int lane = tid & 31;
    const int wid  = tid >> 5;          // 0..15
    const int wm   = (wid >> 2) * 32;   // 4 warps in M
    const int wn   = (wid & 3) * 32;    // 4 warps in N

    // A loader: row = tid/4 (0..127), segment = tid&3 (8 halves / 8 floats)
    const int ar = tid >> 2;
    const int as = tid & 3;
    // B loader: k-row = tid/16 (0..31), n-base = (tid&15)*8
    const int kr = tid >> 4;
    const int nb = (tid & 15) << 3;

    const int nk = (K + BK - 1) / BK;

    uint32_t accc[2][4][2];
    #pragma unroll
    for (int mt = 0; mt < 2; ++mt)
        #pragma unroll
        for (int nt = 0; nt < 4; ++nt) {
            accc[mt][nt][0] = 0u; accc[mt][nt][1] = 0u;
            #pragma unroll
            for (int e = 0; e < 4; ++e) acc[mt][nt][e] = 0.0f;
        }

    float ra[8], rb[8];
    const float* Apf = AF16 ? nullptr : (Af + (size_t)(m0 + ar) * lda);

    auto ldgA_f32 = [&](int k0) {
        #pragma unroll
        for (int i = 0; i < 2; ++i) {
            const int kg = k0 + as * 8 + i * 4;
            if (kg + 3 < K) {
                float4 v = *reinterpret_cast<const float4*>(Apf + kg);
                ra[i*4+0] = v.x; ra[i*4+1] = v.y; ra[i*4+2] = v.z; ra[i*4+3] = v.w;
            } else {
                #pragma unroll
                for (int j = 0; j < 4; ++j)
                    ra[i*4+j] = (kg + j < K) ? Apf[kg + j] : 0.0f;
            }
        }
    };
    auto cpA_f16 = [&](int k0, int buf) {
        const uint32_t d = sb + buf * BUF_BYTES + (uint32_t)(ar * BKP + as * 8) * 2;
        const size_t go = (size_t)(m0 + ar) * lda + k0 + as * 8;
        cp_async16(d + PB_AHI, Ah + go);
        cp_async16(d + PB_ALO, Al + go);
    };
    auto ldgB = [&](int k0) {
        const int kgB = k0 + kr;
        if (kgB < K) {
            const float* Wp = W + (size_t)kgB * ldw + n0 + nb;
            #pragma unroll
            for (int i = 0; i < 2; ++i) {
                float4 v = *reinterpret_cast<const float4*>(Wp + i * 4);
                rb[i*4+0] = v.x; rb[i*4+1] = v.y; rb[i*4+2] = v.z; rb[i*4+3] = v.w;
            }
        } else {
            #pragma unroll
            for (int i = 0; i < 8; ++i) rb[i] = 0.0f;
        }
    };
    auto stA_f32 = [&](int buf) {
        __half* sAhi = reinterpret_cast<__half*>(dyn + buf * BUF_BYTES + PB_AHI);
        __half* sAlo = reinterpret_cast<__half*>(dyn + buf * BUF_BYTES + PB_ALO);
        #pragma unroll
        for (int i = 0; i < 2; ++i) {
            const int kk = as * 8 + i * 4;
            __half h0,l0,h1,l1,h2,l2,h3,l3;
            split_f32(ra[i*4+0], h0, l0); split_f32(ra[i*4+1], h1, l1);
            split_f32(ra[i*4+2], h2, l2); split_f32(ra[i*4+3], h3, l3);
            *reinterpret_cast<__half2*>(&sAhi[ar*BKP + kk])     = __halves2half2(h0, h1);
            *reinterpret_cast<__half2*>(&sAhi[ar*BKP + kk + 2]) = __halves2half2(h2, h3);
            *reinterpret_cast<__half2*>(&sAlo[ar*BKP + kk])     = __halves2half2(l0, l1);
            *reinterpret_cast<__half2*>(&sAlo[ar*BKP + kk + 2]) = __halves2half2(l2, l3);
        }
    };
    auto stB = [&](int buf) {
        __half* sBhi = reinterpret_cast<__half*>(dyn + buf * BUF_BYTES + PB_BHI);
        __half* sBlo = reinterpret_cast<__half*>(dyn + buf * BUF_BYTES + PB_BLO);
        #pragma unroll
        for (int i = 0; i < 2; ++i) {
            const int n = nb + i * 4;
            __half h0,l0,h1,l1,h2,l2,h3,l3;
            split_f32(rb[i*4+0], h0, l0); split_f32(rb[i*4+1], h1, l1);
            split_f32(rb[i*4+2], h2, l2); split_f32(rb[i*4+3], h3, l3);
            *reinterpret_cast<__half2*>(&sBhi[kr*BNP + n])     = __halves2half2(h0, h1);
            *reinterpret_cast<__half2*>(&sBhi[kr*BNP + n + 2]) = __halves2half2(h2, h3);
            *reinterpret_cast<__half2*>(&sBlo[kr*BNP + n])     = __halves2half2(l0, l1);
            *reinterpret_cast<__half2*>(&sBlo[kr*BNP + n + 2]) = __halves2half2(l2, l3);
        }
    };

    // prologue: stage tile 0 into buf 0
    if (AF16) cpA_f16(0, 0); else ldgA_f32(0);
    ldgB(0);
    if (!AF16) stA_f32(0);
    stB(0);
    if (AF16) { cp_async_commit(); cp_async_wait0(); }
    __syncthreads();

    for (int t = 0; t < nk; ++t) {
        const int cur = t & 1, nxt = (t + 1) & 1;
        const bool more = (t + 1) < nk;

        // 1) issue next tile's loads
        if (more) {
            if (AF16) { cpA_f16((t + 1) * BK, nxt); cp_async_commit(); }
            else      { ldgA_f32((t + 1) * BK); }
            ldgB((t + 1) * BK);
        }

        // 2) MMA on current buffer; three 8-wide independent batches per ks
        {
            const uint32_t aHiB = sb + cur * BUF_BYTES + PB_AHI;
            const uint32_t aLoB = sb + cur * BUF_BYTES + PB_ALO;
            const uint32_t bHiB = sb + cur * BUF_BYTES + PB_BHI;
            const uint32_t bLoB = sb + cur * BUF_BYTES + PB_BLO;
            const int l = lane & 15;
            #pragma unroll
            for (int ks = 0; ks < 2; ++ks) {
                uint32_t bh[4][2], bl[4][2];
                #pragma unroll
                for (int nt = 0; nt < 4; ++nt) {
                    const uint32_t off =
                        ((uint32_t)(ks * 16 + l) * BNP + wn + nt * 8) * 2;
                    ldsm_x2t(bh[nt], bHiB + off);
                    ldsm_x2t(bl[nt], bLoB + off);
                }
                uint32_t ah[2][4], al[2][4];
                #pragma unroll
                for (int mt = 0; mt < 2; ++mt) {
                    const uint32_t offa =
                        ((uint32_t)(wm + mt * 16 + l) * BKP + ks * 16 + (lane >> 4) * 8) * 2;
                    ldsm_x4(ah[mt], aHiB + offa);
                    ldsm_x4(al[mt], aLoB + offa);
                }
                // batch 1: hi*hi (8 independent, f32 acc)
                #pragma unroll
                for (int mt = 0; mt < 2; ++mt)
                    #pragma unroll
                    for (int nt = 0; nt < 4; ++nt)
                        mma_f32(acc[mt][nt], ah[mt], bh[nt]);
                // batch 2: hi*lo (8 independent, f16 acc)
                #pragma unroll
                for (int mt = 0; mt < 2; ++mt)
                    #pragma unroll
                    for (int nt = 0; nt < 4; ++nt)
                        mma_f16(accc[mt][nt], ah[mt], bl[nt]);
                // batch 3: lo*hi (dep distance 8 from batch 2)
                #pragma unroll
                for (int mt = 0; mt < 2; ++mt)
                    #pragma unroll
                    for (int nt = 0; nt < 4; ++nt)
                        mma_f16(accc[mt][nt], al[mt], bh[nt]);
            }
        }

        // 3) convert+store next tile in MMA shadow, then publish
        if (more) {
            if (!AF16) stA_f32(nxt);
            stB(nxt);
            if (AF16) cp_async_wait0();
        }
        __syncthreads();
    }

    // merge fp16 correction accumulators
    #pragma unroll
    for (int mt = 0; mt < 2; ++mt)
        #pragma unroll
        for (int nt = 0; nt < 4; ++nt) {
            const __half2 c01 = *reinterpret_cast<const __half2*>(&accc[mt][nt][0]);
            const __half2 c23 = *reinterpret_cast<const __half2*>(&accc[mt][nt][1]);
            acc[mt][nt][0] += __low2float(c01);
            acc[mt][nt][1] += __high2float(c01);
            acc[mt][nt][2] += __low2float(c23);
            acc[mt][nt][3] += __high2float(c23);
        }
}

// ================= stage kernels =================

// stage 1: grouped fc1 (A fp32). grid (2, 8, 32)
__global__ void __launch_bounds__(THREADS, 1) k_fc1g(
    const float* __restrict__ q,  const float* __restrict__ k,
    const float* __restrict__ Wq1, const float* __restrict__ bq1,
    const float* __restrict__ Wk1, const float* __restrict__ bk1)
{
    const int z = blockIdx.z, br = z >> 4, g = z & 15;
    const int m0 = blockIdx.x * BM, n0 = blockIdx.y * BN;

    const float* A    = (br ? k : q) + g * GS_;
    const float* W    = (br ? Wk1 : Wq1) + (size_t)g * GS_ * HID_;
    const float* bias = (br ? bk1 : bq1) + g * HID_;

    float acc[2][4][4];
    gemm_body<false>(A, nullptr, nullptr, G_ * GS_, W, HID_, GS_, m0, n0, acc);

    const int lane = threadIdx.x & 31, wid = threadIdx.x >> 5;
    const int wm = (wid >> 2) * 32, wn = (wid & 3) * 32;
    #pragma unroll
    for (int mt = 0; mt < 2; ++mt) {
        const int r = m0 + wm + mt * 16 + (lane >> 2);
        #pragma unroll
        for (int nt = 0; nt < 4; ++nt) {
            const int c = n0 + wn + nt * 8 + (lane & 3) * 2;
            const float b0 = bias[c], b1 = bias[c + 1];
            const size_t i0 = (size_t)(br * B_ + r) * (G_ * HID_) + (size_t)g * HID_ + c;
            const size_t i1 = i0 + (size_t)8 * (G_ * HID_);
            split_store2(&g_h_hi[i0], &g_h_lo[i0],
                         silu_f(acc[mt][nt][0] + b0), silu_f(acc[mt][nt][1] + b1));
            split_store2(&g_h_hi[i1], &g_h_lo[i1],
                         silu_f(acc[mt][nt][2] + b0), silu_f(acc[mt][nt][3] + b1));
        }
    }
}

// stage 2: grouped fc4 + feature-major interleave (A pre-split). grid (2, 16, 32)
__global__ void __launch_bounds__(THREADS, 1) k_fc4g(
    const float* __restrict__ Wq4, const float* __restrict__ bq4,
    const float* __restrict__ Wk4, const float* __restrict__ bk4)
{
    const int z = blockIdx.z, br = z >> 4, g = z & 15;
    const int m0 = blockIdx.x * BM, n0 = blockIdx.y * BN;

    const __half* Ah  = g_h_hi + (size_t)br * B_ * G_ * HID_ + (size_t)g * HID_;
    const __half* Al  = g_h_lo + (size_t)br * B_ * G_ * HID_ + (size_t)g * HID_;
    const float* W    = (br ? Wk4 : Wq4) + (size_t)g * HID_ * FEAT_;
    const float* bias = (br ? bk4 : bq4) + g * FEAT_;

    float acc[2][4][4];
    gemm_body<true>(nullptr, Ah, Al, G_ * HID_, W, FEAT_, HID_, m0, n0, acc);

    const int lane = threadIdx.x & 31, wid = threadIdx.x >> 5;
    const int wm = (wid >> 2) * 32, wn = (wid & 3) * 32;
    #pragma unroll
    for (int mt = 0; mt < 2; ++mt) {
        const int r = m0 + wm + mt * 16 + (lane >> 2);
        const size_t rb0 = (size_t)(br * B_ + r)     * (G_ * FEAT_) + g;
        const size_t rb1 = (size_t)(br * B_ + r + 8) * (G_ * FEAT_) + g;
        #pragma unroll
        for (int nt = 0; nt < 4; ++nt) {
            const int c = n0 + wn + nt * 8 + (lane & 3) * 2;
            const float b0 = bias[c], b1 = bias[c + 1];
            const float v0 = silu_f(acc[mt][nt][0] + b0);
            const float v1 = silu_f(acc[mt][nt][1] + b1);
            const float v2 = silu_f(acc[mt][nt][2] + b0);
            const float v3 = silu_f(acc[mt][nt][3] + b1);
            __half h, l;
            split_f32(v0, h, l); g_f_hi[rb0 + (size_t)c * G_] = h;       g_f_lo[rb0 + (size_t)c * G_] = l;
            split_f32(v1, h, l); g_f_hi[rb0 + (size_t)(c + 1) * G_] = h; g_f_lo[rb0 + (size_t)(c + 1) * G_] = l;
            split_f32(v2, h, l); g_f_hi[rb1 + (size_t)c * G_] = h;       g_f_lo[rb1 + (size_t)c * G_] = l;
            split_f32(v3, h, l); g_f_hi[rb1 + (size_t)(c + 1) * G_] = h; g_f_lo[rb1 + (size_t)(c + 1) * G_] = l;
        }
    }
}

// stage 3: global fc1 split-K (A pre-split). grid (4, 8, NSPL)
__global__ void __launch_bounds__(THREADS, 1) k_gf1(const float* __restrict__ Wg1)
{
    const int s = blockIdx.z;
    const int m0 = blockIdx.x * BM, n0 = blockIdx.y * BN;

    const __half* Ah = g_f_hi + (size_t)s * KSPL;
    const __half* Al = g_f_lo + (size_t)s * KSPL;
    const float*  W  = Wg1 + (size_t)s * KSPL * HID_;

    float acc[2][4][4];
    gemm_body<true>(nullptr, Ah, Al, G_ * FEAT_, W, HID_, KSPL, m0, n0, acc);

    const int lane = threadIdx.x & 31, wid = threadIdx.x >> 5;
    const int wm = (wid >> 2) * 32, wn = (wid & 3) * 32;
    float* P = g_part + (size_t)s * (2 * B_ * HID_);
    #pragma unroll
    for (int mt = 0; mt < 2; ++mt) {
        const int r = m0 + wm + mt * 16 + (lane >> 2);
        #pragma unroll
        for (int nt = 0; nt < 4; ++nt) {
            const int c = n0 + wn + nt * 8 + (lane & 3) * 2;
            P[(size_t)r * HID_ + c]           = acc[mt][nt][0];
            P[(size_t)r * HID_ + c + 1]       = acc[mt][nt][1];
            P[(size_t)(r + 8) * HID_ + c]     = acc[mt][nt][2];
            P[(size_t)(r + 8) * HID_ + c + 1] = acc[mt][nt][3];
        }
    }
}

// reduce NSPL partials + bias + silu -> pre-split g_hg
__global__ void __launch_bounds__(256) k_reduce_silu(const float* __restrict__ bg1)
{
    const int idx = blockIdx.x * blockDim.x + threadIdx.x;
    if (idx >= 2 * B_ * HID_) return;
    const int col = idx & (HID_ - 1);
    float v = bg1[col];
    #pragma unroll
    for (int s = 0; s < NSPL; ++s)
        v += g_part[(size_t)s * (2 * B_ * HID_) + idx];
    v = silu_f(v);
    __half h, l;
    split_f32(v, h, l);
    g_hg_hi[idx] = h;
    g_hg_lo[idx] = l;
}

// stage 4: global fc4 (A pre-split). grid (4, 16)
__global__ void __launch_bounds__(THREADS, 1) k_gf4(
    const float* __restrict__ Wg4, const float* __restrict__ bg4)
{
    const int m0 = blockIdx.x * BM, n0 = blockIdx.y * BN;

    float acc[2][4][4];
    gemm_body<true>(nullptr, g_hg_hi, g_hg_lo, HID_, Wg4, FEAT_, HID_, m0, n0, acc);

    const int lane = threadIdx.x & 31, wid = threadIdx.x >> 5;
    const int wm = (wid >> 2) * 32, wn = (wid & 3) * 32;
    #pragma unroll
    for (int mt = 0; mt < 2; ++mt) {
        const int r = m0 + wm + mt * 16 + (lane >> 2);
        float* C0 = g_o + (size_t)r * FEAT_;
        float* C1 = g_o + (size_t)(r + 8) * FEAT_;
        #pragma unroll
        for (int nt = 0; nt < 4; ++nt) {
            const int c = n0 + wn + nt * 8 + (lane & 3) * 2;
            const float b0 = bg4[c], b1 = bg4[c + 1];
            C0[c]     = silu_f(acc[mt][nt][0] + b0);
            C0[c + 1] = silu_f(acc[mt][nt][1] + b1);
            C1[c]     = silu_f(acc[mt][nt][2] + b0);
            C1[c + 1] = silu_f(acc[mt][nt][3] + b1);
        }
    }
}

// stage 5: per-batch dot
__global__ void __launch_bounds__(256) k_dot()
{
    const int b = blockIdx.x;
    const int t = threadIdx.x;
    const float* qo = g_o + (size_t)b * FEAT_;
    const float* ko = g_o + (size_t)(B_ + b) * FEAT_;
    float s = 0.0f;
    for (int i = t; i < FEAT_; i += 256)
        s = fmaf(qo[i], ko[i], s);
    __shared__ float sh[256];
    sh[t] = s;
    __syncthreads();
    for (int off = 128; off > 0; off >>= 1) {
        if (t < off) sh[t] += sh[t + off];
        __syncthreads();
    }
    if (t == 0) g_scores[b] = sh[0];
}

// stage 6: softmax over batch
__global__ void __launch_bounds__(256) k_softmax(float* __restrict__ out)
{
    const int t = threadIdx.x;
    __shared__ float sh[256];
    float v = g_scores[t];
    sh[t] = v;
    __syncthreads();
    for (int off = 128; off > 0; off >>= 1) {
        if (t < off) sh[t] = fmaxf(sh[t], sh[t + off]);
        __syncthreads();
    }
    const float m = sh[0];
    __syncthreads();
    const float e = expf(v - m);
    sh[t] = e;
    __syncthreads();
    for (int off = 128; off > 0; off >>= 1) {
        if (t < off) sh[t] += sh[t + off];
        __syncthreads();
    }
    out[t] = e / sh[0];
}

// ================= launch =================
extern "C" void kernel_launch(void* const* d_in, const int* in_sizes, int n_in,
                              void* d_out, int out_size)
{
    const float* q   = (const float*)d_in[0];
    const float* k   = (const float*)d_in[1];
    const float* Wq1 = (const float*)d_in[2];
    const float* bq1 = (const float*)d_in[3];
    const float* Wq4 = (const float*)d_in[4];
    const float* bq4 = (const float*)d_in[5];
    const float* Wk1 = (const float*)d_in[6];
    const float* bk1 = (const float*)d_in[7];
    const float* Wk4 = (const float*)d_in[8];
    const float* bk4 = (const float*)d_in[9];
    const float* Wg1 = (const float*)d_in[10];
    const float* bg1 = (const float*)d_in[11];
    const float* Wg4 = (const float*)d_in[12];
    const float* bg4 = (const float*)d_in[13];
    float* out = (float*)d_out;

    cudaFuncSetAttribute(k_fc1g, cudaFuncAttributeMaxDynamicSharedMemorySize, SMEM_TOTAL);
    cudaFuncSetAttribute(k_fc4g, cudaFuncAttributeMaxDynamicSharedMemorySize, SMEM_TOTAL);
    cudaFuncSetAttribute(k_gf1,  cudaFuncAttributeMaxDynamicSharedMemorySize, SMEM_TOTAL);
    cudaFuncSetAttribute(k_gf4,  cudaFuncAttributeMaxDynamicSharedMemorySize, SMEM_TOTAL);

    k_fc1g<<<dim3(2, 8, 2 * G_),  THREADS, SMEM_TOTAL>>>(q, k, Wq1, bq1, Wk1, bk1);
    k_fc4g<<<dim3(2, 16, 2 * G_), THREADS, SMEM_TOTAL>>>(Wq4, bq4, Wk4, bk4);
    k_gf1<<<dim3(4, 8, NSPL),     THREADS, SMEM_TOTAL>>>(Wg1);
    k_reduce_silu<<<(2 * B_ * HID_) / 256, 256>>>(bg1);
    k_gf4<<<dim3(4, 16, 1),       THREADS, SMEM_TOTAL>>>(Wg4, bg4);
    k_dot<<<B_, 256>>>();
    k_softmax<<<1, 256>>>(out);
}

// round 7
// speedup vs baseline: 2.6197x; 1.0319x over previous
#include <cuda_runtime.h>
#include <cuda_fp16.h>
#include <math.h>
#include <stdint.h>

#define B_    256
#define G_    16
#define GS_   588
#define HID_  1024
#define FEAT_ 2048
#define NSPL  32
#define KSPL  ((G_ * FEAT_) / NSPL)   // 1024
#define NSPL4 8
#define KSPL4 (HID_ / NSPL4)          // 128

#define THREADS 512
#define BM 128
#define BN 128
#define BK 64
#define BKP 72     // padded A row (halves): 144B stride, conflict-free LDSM
#define BNP 136    // padded B row (halves): 272B stride, conflict-free LDSM

// per-buffer SMEM layout (bytes)
#define PB_AHI 0
#define PB_ALO 18432
#define PB_BHI 36864
#define PB_BLO 54272
#define BUF_BYTES 71680
#define SMEM_TOTAL (2 * BUF_BYTES)   // 143360

// ---------------- scratch (device globals) ----------------
__device__ __half g_h_hi[(size_t)2 * B_ * G_ * HID_];
__device__ __half g_h_lo[(size_t)2 * B_ * G_ * HID_];
__device__ __half g_f_hi[(size_t)2 * B_ * G_ * FEAT_];
__device__ __half g_f_lo[(size_t)2 * B_ * G_ * FEAT_];
__device__ float  g_part[(size_t)NSPL * 2 * B_ * HID_];    // 67 MB
__device__ float  g_part4[(size_t)NSPL4 * 2 * B_ * FEAT_]; // 33.5 MB
__device__ __half g_hg_hi[(size_t)2 * B_ * HID_];
__device__ __half g_hg_lo[(size_t)2 * B_ * HID_];
__device__ float  g_o[(size_t)2 * B_ * FEAT_];
__device__ float  g_scores[B_];

__device__ __forceinline__ float silu_f(float v) {
    return v / (1.0f + __expf(-v));
}
__device__ __forceinline__ uint32_t smem_to_u32(const void* p) {
    uint32_t a;
    asm("{ .reg .u64 t; cvta.to.shared.u64 t, %1; cvt.u32.u64 %0, t; }"
        : "=r"(a) : "l"(p));
    return a;
}

// ---- family-portable primitives (valid on compute_103) ----
__device__ __forceinline__ void ldsm_x4(uint32_t* r, uint32_t addr) {
    asm volatile("ldmatrix.sync.aligned.m8n8.x4.shared.b16 {%0,%1,%2,%3}, [%4];"
        : "=r"(r[0]), "=r"(r[1]), "=r"(r[2]), "=r"(r[3]) : "r"(addr));
}
__device__ __forceinline__ void ldsm_x2t(uint32_t* r, uint32_t addr) {
    asm volatile("ldmatrix.sync.aligned.m8n8.x2.trans.shared.b16 {%0,%1}, [%2];"
        : "=r"(r[0]), "=r"(r[1]) : "r"(addr));
}
__device__ __forceinline__ void mma_f32(float* d, const uint32_t* a, const uint32_t* b) {
    asm volatile(
        "mma.sync.aligned.m16n8k16.row.col.f32.f16.f16.f32 "
        "{%0,%1,%2,%3}, {%4,%5,%6,%7}, {%8,%9}, {%0,%1,%2,%3};"
        : "+f"(d[0]), "+f"(d[1]), "+f"(d[2]), "+f"(d[3])
        : "r"(a[0]), "r"(a[1]), "r"(a[2]), "r"(a[3]), "r"(b[0]), "r"(b[1]));
}
__device__ __forceinline__ void mma_f16(uint32_t* d, const uint32_t* a, const uint32_t* b) {
    asm volatile(
        "mma.sync.aligned.m16n8k16.row.col.f16.f16.f16.f16 "
        "{%0,%1}, {%2,%3,%4,%5}, {%6,%7}, {%0,%1};"
        : "+r"(d[0]), "+r"(d[1])
        : "r"(a[0]), "r"(a[1]), "r"(a[2]), "r"(a[3]), "r"(b[0]), "r"(b[1]));
}
__device__ __forceinline__ void cp_async16(uint32_t dst, const void* src) {
    asm volatile("cp.async.ca.shared.global [%0], [%1], 16;" :: "r"(dst), "l"(src));
}
__device__ __forceinline__ void cp_async_commit() {
    asm volatile("cp.async.commit_group;" ::: "memory");
}
__device__ __forceinline__ void cp_async_wait0() {
    asm volatile("cp.async.wait_group 0;" ::: "memory");
}

__device__ __forceinline__ void split_f32(float x, __half& hi, __half& lo) {
    hi = __float2half_rn(x);
    lo = __float2half_rn(x - __half2float(hi));
}
__device__ __forceinline__ void split_store2(__half* hi, __half* lo, float v0, float v1) {
    __half h0, l0, h1, l1;
    split_f32(v0, h0, l0); split_f32(v1, h1, l1);
    *reinterpret_cast<__half2*>(hi) = __halves2half2(h0, h1);
    *reinterpret_cast<__half2*>(lo) = __halves2half2(l0, l1);
}
// split 4 floats -> one uint2 (4 halves) each for hi and lo
__device__ __forceinline__ void split4(const float* v, uint32_t* hi2, uint32_t* lo2) {
    __half h0,l0,h1,l1,h2,l2,h3,l3;
    split_f32(v[0], h0, l0); split_f32(v[1], h1, l1);
    split_f32(v[2], h2, l2); split_f32(v[3], h3, l3);
    __half2 a = __halves2half2(h0, h1), b = __halves2half2(h2, h3);
    __half2 c = __halves2half2(l0, l1), d = __halves2half2(l2, l3);
    hi2[0] = *reinterpret_cast<uint32_t*>(&a);
    hi2[1] = *reinterpret_cast<uint32_t*>(&b);
    lo2[0] = *reinterpret_cast<uint32_t*>(&c);
    lo2[1] = *reinterpret_cast<uint32_t*>(&d);
}

// ---------------- GEMM body (512 threads, warp grid 4x4, 32x32/warp, BK=64) ----
template<bool AF16>
__device__ __forceinline__ void gemm_body(
    const float* __restrict__ Af,
    const __half* __restrict__ Ah, const __half* __restrict__ Al, int lda,
    const float* __restrict__ W, int ldw,
    int K, int m0, int n0, float acc[2][4][4])
{
    extern __shared__ char dyn[];
    const uint32_t sb = smem_to_u32(dyn);

    const int tid  = threadIdx.x;
    const int lane = tid & 31;
    const int wid  = tid >> 5;          // 0..15
    const int wm   = (wid >> 2) * 32;
    const int wn   = (wid & 3) * 32;

    // A loader: row = tid/4 (0..127), 16 k-elems from (tid&3)*16
    const int ar = tid >> 2;
    const int as = (tid & 3) << 4;
    // B loader: k-row = tid/8 (0..63), 16 n-elems from (tid&7)*16
    const int kr = tid >> 3;
    const int nb = (tid & 7) << 4;

    const int nk = (K + BK - 1) / BK;

    uint32_t accc[2][4][2];
    #pragma unroll
    for (int mt = 0; mt < 2; ++mt)
        #pragma unroll
        for (int nt = 0; nt < 4; ++nt) {
            accc[mt][nt][0] = 0u; accc[mt][nt][1] = 0u;
            #pragma unroll
            for (int e = 0; e < 4; ++e) acc[mt][nt][e] = 0.0f;
        }

    float ra[16], rb[16];
    const float* Apf = AF16 ? nullptr : (Af + (size_t)(m0 + ar) * lda);

    auto ldgA_f32 = [&](int k0) {
        #pragma unroll
        for (int i = 0; i < 4; ++i) {
            const int kg = k0 + as + i * 4;
            if (kg + 3 < K) {
                float4 v = *reinterpret_cast<const float4*>(Apf + kg);
                ra[i*4+0] = v.x; ra[i*4+1] = v.y; ra[i*4+2] = v.z; ra[i*4+3] = v.w;
            } else {
                #pragma unroll
                for (int j = 0; j < 4; ++j)
                    ra[i*4+j] = (kg + j < K) ? Apf[kg + j] : 0.0f;
            }
        }
    };
    auto cpA_f16 = [&](int k0, int buf) {
        const uint32_t d = sb + buf * BUF_BYTES + (uint32_t)(ar * BKP + as) * 2;
        const size_t go = (size_t)(m0 + ar) * lda + k0 + as;
        cp_async16(d + PB_AHI,      Ah + go);
        cp_async16(d + PB_AHI + 16, Ah + go + 8);
        cp_async16(d + PB_ALO,      Al + go);
        cp_async16(d + PB_ALO + 16, Al + go + 8);
    };
    auto ldgB = [&](int k0) {
        const int kgB = k0 + kr;
        if (kgB < K) {
            const float* Wp = W + (size_t)kgB * ldw + n0 + nb;
            #pragma unroll
            for (int i = 0; i < 4; ++i) {
                float4 v = *reinterpret_cast<const float4*>(Wp + i * 4);
                rb[i*4+0] = v.x; rb[i*4+1] = v.y; rb[i*4+2] = v.z; rb[i*4+3] = v.w;
            }
        } else {
            #pragma unroll
            for (int i = 0; i < 16; ++i) rb[i] = 0.0f;
        }
    };
    auto stA_f32 = [&](int buf) {
        char* base = dyn + buf * BUF_BYTES;
        uint32_t hi2[4], lo2[4];
        split4(ra,     hi2,     lo2);
        split4(ra + 4, hi2 + 2, lo2 + 2);
        *reinterpret_cast<uint4*>(base + PB_AHI + (ar*BKP + as)*2) =
            make_uint4(hi2[0], hi2[1], hi2[2], hi2[3]);
        *reinterpret_cast<uint4*>(base + PB_ALO + (ar*BKP + as)*2) =
            make_uint4(lo2[0], lo2[1], lo2[2], lo2[3]);
        split4(ra + 8,  hi2,     lo2);
        split4(ra + 12, hi2 + 2, lo2 + 2);
        *reinterpret_cast<uint4*>(base + PB_AHI + (ar*BKP + as + 8)*2) =
            make_uint4(hi2[0], hi2[1], hi2[2], hi2[3]);
        *reinterpret_cast<uint4*>(base + PB_ALO + (ar*BKP + as + 8)*2) =
            make_uint4(lo2[0], lo2[1], lo2[2], lo2[3]);
    };
    auto stB = [&](int buf) {
        char* base = dyn + buf * BUF_BYTES;
        uint32_t hi2[4], lo2[4];
        split4(rb,     hi2,     lo2);
        split4(rb + 4, hi2 + 2, lo2 + 2);
        *reinterpret_cast<uint4*>(base + PB_BHI + (kr*BNP + nb)*2) =
            make_uint4(hi2[0], hi2[1], hi2[2], hi2[3]);
        *reinterpret_cast<uint4*>(base + PB_BLO + (kr*BNP + nb)*2) =
            make_uint4(lo2[0], lo2[1], lo2[2], lo2[3]);
        split4(rb + 8,  hi2,     lo2);
        split4(rb + 12, hi2 + 2, lo2 + 2);
        *reinterpret_cast<uint4*>(base + PB_BHI + (kr*BNP + nb + 8)*2) =
            make_uint4(hi2[0], hi2[1], hi2[2], hi2[3]);
        *reinterpret_cast<uint4*>(base + PB_BLO + (kr*BNP + nb + 8)*2) =
            make_uint4(lo2[0], lo2[1], lo2[2], lo2[3]);
    };

    // prologue: stage buffer 0
    if (AF16) cpA_f16(0, 0); else ldgA_f32(0);
    ldgB(0);
    if (!AF16) stA_f32(0);
    stB(0);
    if (AF16) { cp_async_commit(); cp_async_wait0(); }
    __syncthreads();

    for (int t = 0; t < nk; ++t) {
        const int cur = t & 1, nxt = (t + 1) & 1;
        const bool more = (t + 1) < nk;

        if (more) {
            if (AF16) { cpA_f16((t + 1) * BK, nxt); cp_async_commit(); }
            else      { ldgA_f32((t + 1) * BK); }
            ldgB((t + 1) * BK);
        }

        {
            const uint32_t aHiB = sb + cur * BUF_BYTES + PB_AHI;
            const uint32_t aLoB = sb + cur * BUF_BYTES + PB_ALO;
            const uint32_t bHiB = sb + cur * BUF_BYTES + PB_BHI;
            const uint32_t bLoB = sb + cur * BUF_BYTES + PB_BLO;
            const int l = lane & 15;
            #pragma unroll
            for (int ks = 0; ks < 4; ++ks) {
                uint32_t bh[4][2], bl[4][2];
                #pragma unroll
                for (int nt = 0; nt < 4; ++nt) {
                    const uint32_t off =
                        ((uint32_t)(ks * 16 + l) * BNP + wn + nt * 8) * 2;
                    ldsm_x2t(bh[nt], bHiB + off);
                    ldsm_x2t(bl[nt], bLoB + off);
                }
                uint32_t ah[2][4], al[2][4];
                #pragma unroll
                for (int mt = 0; mt < 2; ++mt) {
                    const uint32_t offa =
                        ((uint32_t)(wm + mt * 16 + l) * BKP + ks * 16 + (lane >> 4) * 8) * 2;
                    ldsm_x4(ah[mt], aHiB + offa);
                    ldsm_x4(al[mt], aLoB + offa);
                }
                #pragma unroll
                for (int mt = 0; mt < 2; ++mt)
                    #pragma unroll
                    for (int nt = 0; nt < 4; ++nt)
                        mma_f32(acc[mt][nt], ah[mt], bh[nt]);
                #pragma unroll
                for (int mt = 0; mt < 2; ++mt)
                    #pragma unroll
                    for (int nt = 0; nt < 4; ++nt)
                        mma_f16(accc[mt][nt], ah[mt], bl[nt]);
                #pragma unroll
                for (int mt = 0; mt < 2; ++mt)
                    #pragma unroll
                    for (int nt = 0; nt < 4; ++nt)
                        mma_f16(accc[mt][nt], al[mt], bh[nt]);
            }
        }

        if (more) {
            if (!AF16) stA_f32(nxt);
            stB(nxt);
            if (AF16) cp_async_wait0();
        }
        __syncthreads();
    }

    #pragma unroll
    for (int mt = 0; mt < 2; ++mt)
        #pragma unroll
        for (int nt = 0; nt < 4; ++nt) {
            const __half2 c01 = *reinterpret_cast<const __half2*>(&accc[mt][nt][0]);
            const __half2 c23 = *reinterpret_cast<const __half2*>(&accc[mt][nt][1]);
            acc[mt][nt][0] += __low2float(c01);
            acc[mt][nt][1] += __high2float(c01);
            acc[mt][nt][2] += __low2float(c23);
            acc[mt][nt][3] += __high2float(c23);
        }
}

// ================= stage kernels =================

// stage 1: grouped fc1 (A fp32). grid (2, 8, 32)
__global__ void __launch_bounds__(THREADS, 1) k_fc1g(
    const float* __restrict__ q,  const float* __restrict__ k,
    const float* __restrict__ Wq1, const float* __restrict__ bq1,
    const float* __restrict__ Wk1, const float* __restrict__ bk1)
{
    const int z = blockIdx.z, br = z >> 4, g = z & 15;
    const int m0 = blockIdx.x * BM, n0 = blockIdx.y * BN;

    const float* A    = (br ? k : q) + g * GS_;
    const float* W    = (br ? Wk1 : Wq1) + (size_t)g * GS_ * HID_;
    const float* bias = (br ? bk1 : bq1) + g * HID_;

    float acc[2][4][4];
    gemm_body<false>(A, nullptr, nullptr, G_ * GS_, W, HID_, GS_, m0, n0, acc);

    const int lane = threadIdx.x & 31, wid = threadIdx.x >> 5;
    const int wm = (wid >> 2) * 32, wn = (wid & 3) * 32;
    #pragma unroll
    for (int mt = 0; mt < 2; ++mt) {
        const int r = m0 + wm + mt * 16 + (lane >> 2);
        #pragma unroll
        for (int nt = 0; nt < 4; ++nt) {
            const int c = n0 + wn + nt * 8 + (lane & 3) * 2;
            const float b0 = bias[c], b1 = bias[c + 1];
            const size_t i0 = (size_t)(br * B_ + r) * (G_ * HID_) + (size_t)g * HID_ + c;
            const size_t i1 = i0 + (size_t)8 * (G_ * HID_);
            split_store2(&g_h_hi[i0], &g_h_lo[i0],
                         silu_f(acc[mt][nt][0] + b0), silu_f(acc[mt][nt][1] + b1));
            split_store2(&g_h_hi[i1], &g_h_lo[i1],
                         silu_f(acc[mt][nt][2] + b0), silu_f(acc[mt][nt][3] + b1));
        }
    }
}

// stage 2: grouped fc4 + feature-major interleave (A pre-split). grid (2, 16, 32)
__global__ void __launch_bounds__(THREADS, 1) k_fc4g(
    const float* __restrict__ Wq4, const float* __restrict__ bq4,
    const float* __restrict__ Wk4, const float* __restrict__ bk4)
{
    const int z = blockIdx.z, br = z >> 4, g = z & 15;
    const int m0 = blockIdx.x * BM, n0 = blockIdx.y * BN;

    const __half* Ah  = g_h_hi + (size_t)br * B_ * G_ * HID_ + (size_t)g * HID_;
    const __half* Al  = g_h_lo + (size_t)br * B_ * G_ * HID_ + (size_t)g * HID_;
    const float* W    = (br ? Wk4 : Wq4) + (size_t)g * HID_ * FEAT_;
    const float* bias = (br ? bk4 : bq4) + g * FEAT_;

    float acc[2][4][4];
    gemm_body<true>(nullptr, Ah, Al, G_ * HID_, W, FEAT_, HID_, m0, n0, acc);

    const int lane = threadIdx.x & 31, wid = threadIdx.x >> 5;
    const int wm = (wid >> 2) * 32, wn = (wid & 3) * 32;
    #pragma unroll
    for (int mt = 0; mt < 2; ++mt) {
        const int r = m0 + wm + mt * 16 + (lane >> 2);
        const size_t rb0 = (size_t)(br * B_ + r)     * (G_ * FEAT_) + g;
        const size_t rb1 = (size_t)(br * B_ + r + 8) * (G_ * FEAT_) + g;
        #pragma unroll
        for (int nt = 0; nt < 4; ++nt) {
            const int c = n0 + wn + nt * 8 + (lane & 3) * 2;
            const float b0 = bias[c], b1 = bias[c + 1];
            const float v0 = silu_f(acc[mt][nt][0] + b0);
            const float v1 = silu_f(acc[mt][nt][1] + b1);
            const float v2 = silu_f(acc[mt][nt][2] + b0);
            const float v3 = silu_f(acc[mt][nt][3] + b1);
            __half h, l;
            split_f32(v0, h, l); g_f_hi[rb0 + (size_t)c * G_] = h;       g_f_lo[rb0 + (size_t)c * G_] = l;
            split_f32(v1, h, l); g_f_hi[rb0 + (size_t)(c + 1) * G_] = h; g_f_lo[rb0 + (size_t)(c + 1) * G_] = l;
            split_f32(v2, h, l); g_f_hi[rb1 + (size_t)c * G_] = h;       g_f_lo[rb1 + (size_t)c * G_] = l;
            split_f32(v3, h, l); g_f_hi[rb1 + (size_t)(c + 1) * G_] = h; g_f_lo[rb1 + (size_t)(c + 1) * G_] = l;
        }
    }
}

// stage 3: global fc1 split-K. grid (4, 8, NSPL=32)
__global__ void __launch_bounds__(THREADS, 1) k_gf1(const float* __restrict__ Wg1)
{
    const int s = blockIdx.z;
    const int m0 = blockIdx.x * BM, n0 = blockIdx.y * BN;

    const __half* Ah = g_f_hi + (size_t)s * KSPL;
    const __half* Al = g_f_lo + (size_t)s * KSPL;
    const float*  W  = Wg1 + (size_t)s * KSPL * HID_;

    float acc[2][4][4];
    gemm_body<true>(nullptr, Ah, Al, G_ * FEAT_, W, HID_, KSPL, m0, n0, acc);

    const int lane = threadIdx.x & 31, wid = threadIdx.x >> 5;
    const int wm = (wid >> 2) * 32, wn = (wid & 3) * 32;
    float* P = g_part + (size_t)s * (2 * B_ * HID_);
    #pragma unroll
    for (int mt = 0; mt < 2; ++mt) {
        const int r = m0 + wm + mt * 16 + (lane >> 2);
        #pragma unroll
        for (int nt = 0; nt < 4; ++nt) {
            const int c = n0 + wn + nt * 8 + (lane & 3) * 2;
            P[(size_t)r * HID_ + c]           = acc[mt][nt][0];
            P[(size_t)r * HID_ + c + 1]       = acc[mt][nt][1];
            P[(size_t)(r + 8) * HID_ + c]     = acc[mt][nt][2];
            P[(size_t)(r + 8) * HID_ + c + 1] = acc[mt][nt][3];
        }
    }
}

// reduce NSPL partials + bias + silu -> pre-split g_hg
__global__ void __launch_bounds__(256) k_reduce_silu(const float* __restrict__ bg1)
{
    const int idx = blockIdx.x * blockDim.x + threadIdx.x;
    if (idx >= 2 * B_ * HID_) return;
    const int col = idx & (HID_ - 1);
    float v = bg1[col];
    #pragma unroll
    for (int s = 0; s < NSPL; ++s)
        v += g_part[(size_t)s * (2 * B_ * HID_) + idx];
    v = silu_f(v);
    __half h, l;
    split_f32(v, h, l);
    g_hg_hi[idx] = h;
    g_hg_lo[idx] = l;
}

// stage 4: global fc4 split-K (A pre-split). grid (4, 16, NSPL4=8)
__global__ void __launch_bounds__(THREADS, 1) k_gf4(const float* __restrict__ Wg4)
{
    const int s = blockIdx.z;
    const int m0 = blockIdx.x * BM, n0 = blockIdx.y * BN;

    const __half* Ah = g_hg_hi + (size_t)s * KSPL4;
    const __half* Al = g_hg_lo + (size_t)s * KSPL4;
    const float*  W  = Wg4 + (size_t)s * KSPL4 * FEAT_;

    float acc[2][4][4];
    gemm_body<true>(nullptr, Ah, Al, HID_, W, FEAT_, KSPL4, m0, n0, acc);

    const int lane = threadIdx.x & 31, wid = threadIdx.x >> 5;
    const int wm = (wid >> 2) * 32, wn = (wid & 3) * 32;
    float* P = g_part4 + (size_t)s * (2 * B_ * FEAT_);
    #pragma unroll
    for (int mt = 0; mt < 2; ++mt) {
        const int r = m0 + wm + mt * 16 + (lane >> 2);
        #pragma unroll
        for (int nt = 0; nt < 4; ++nt) {
            const int c = n0 + wn + nt * 8 + (lane & 3) * 2;
            P[(size_t)r * FEAT_ + c]           = acc[mt][nt][0];
            P[(size_t)r * FEAT_ + c + 1]       = acc[mt][nt][1];
            P[(size_t)(r + 8) * FEAT_ + c]     = acc[mt][nt][2];
            P[(size_t)(r + 8) * FEAT_ + c + 1] = acc[mt][nt][3];
        }
    }
}

// reduce NSPL4 partials + bias + silu -> g_o
__global__ void __launch_bounds__(256) k_reduce4(const float* __restrict__ bg4)
{
    const int idx = blockIdx.x * blockDim.x + threadIdx.x;
    if (idx >= 2 * B_ * FEAT_) return;
    const int col = idx & (FEAT_ - 1);
    float v = bg4[col];
    #pragma unroll
    for (int s = 0; s < NSPL4; ++s)
        v += g_part4[(size_t)s * (2 * B_ * FEAT_) + idx];
    g_o[idx] = silu_f(v);
}

// stage 5: per-batch dot
__global__ void __launch_bounds__(256) k_dot()
{
    const int b = blockIdx.x;
    const int t = threadIdx.x;
    const float* qo = g_o + (size_t)b * FEAT_;
    const float* ko = g_o + (size_t)(B_ + b) * FEAT_;
    float s = 0.0f;
    for (int i = t; i < FEAT_; i += 256)
        s = fmaf(qo[i], ko[i], s);
    __shared__ float sh[256];
    sh[t] = s;
    __syncthreads();
    for (int off = 128; off > 0; off >>= 1) {
        if (t < off) sh[t] += sh[t + off];
        __syncthreads();
    }
    if (t == 0) g_scores[b] = sh[0];
}

// stage 6: softmax over batch
__global__ void __launch_bounds__(256) k_softmax(float* __restrict__ out)
{
    const int t = threadIdx.x;
    __shared__ float sh[256];
    float v = g_scores[t];
    sh[t] = v;
    __syncthreads();
    for (int off = 128; off > 0; off >>= 1) {
        if (t < off) sh[t] = fmaxf(sh[t], sh[t + off]);
        __syncthreads();
    }
    const float m = sh[0];
    __syncthreads();
    const float e = expf(v - m);
    sh[t] = e;
    __syncthreads();
    for (int off = 128; off > 0; off >>= 1) {
        if (t < off) sh[t] += sh[t + off];
        __syncthreads();
    }
    out[t] = e / sh[0];
}

// ================= launch =================
extern "C" void kernel_launch(void* const* d_in, const int* in_sizes, int n_in,
                              void* d_out, int out_size)
{
    const float* q   = (const float*)d_in[0];
    const float* k   = (const float*)d_in[1];
    const float* Wq1 = (const float*)d_in[2];
    const float* bq1 = (const float*)d_in[3];
    const float* Wq4 = (const float*)d_in[4];
    const float* bq4 = (const float*)d_in[5];
    const float* Wk1 = (const float*)d_in[6];
    const float* bk1 = (const float*)d_in[7];
    const float* Wk4 = (const float*)d_in[8];
    const float* bk4 = (const float*)d_in[9];
    const float* Wg1 = (const float*)d_in[10];
    const float* bg1 = (const float*)d_in[11];
    const float* Wg4 = (const float*)d_in[12];
    const float* bg4 = (const float*)d_in[13];
    float* out = (float*)d_out;

    cudaFuncSetAttribute(k_fc1g, cudaFuncAttributeMaxDynamicSharedMemorySize, SMEM_TOTAL);
    cudaFuncSetAttribute(k_fc4g, cudaFuncAttributeMaxDynamicSharedMemorySize, SMEM_TOTAL);
    cudaFuncSetAttribute(k_gf1,  cudaFuncAttributeMaxDynamicSharedMemorySize, SMEM_TOTAL);
    cudaFuncSetAttribute(k_gf4,  cudaFuncAttributeMaxDynamicSharedMemorySize, SMEM_TOTAL);

    k_fc1g<<<dim3(2, 8, 2 * G_),   THREADS, SMEM_TOTAL>>>(q, k, Wq1, bq1, Wk1, bk1);
    k_fc4g<<<dim3(2, 16, 2 * G_),  THREADS, SMEM_TOTAL>>>(Wq4, bq4, Wk4, bk4);
    k_gf1<<<dim3(4, 8, NSPL),      THREADS, SMEM_TOTAL>>>(Wg1);
    k_reduce_silu<<<(2 * B_ * HID_) / 256, 256>>>(bg1);
    k_gf4<<<dim3(4, 16, NSPL4),    THREADS, SMEM_TOTAL>>>(Wg4);
    k_reduce4<<<(2 * B_ * FEAT_) / 256, 256>>>(bg4);
    k_dot<<<B_, 256>>>();
    k_softmax<<<1, 256>>>(out);
}

// round 8
// speedup vs baseline: 2.6435x; 1.0091x over previous
#include <cuda_runtime.h>
#include <cuda_fp16.h>
#include <math.h>
#include <stdint.h>

#define B_    256
#define G_    16
#define GS_   588
#define HID_  1024
#define FEAT_ 2048
#define NSPL  32
#define KSPL  ((G_ * FEAT_) / NSPL)   // 1024
#define NSPL4 8
#define KSPL4 (HID_ / NSPL4)          // 128

#define THREADS 512
#define BM 128
#define BN 128
#define BK 64
#define BKP 72     // padded A row (halves): 144B stride, conflict-free LDSM
#define BNP 136    // padded B row (halves): 272B stride, conflict-free LDSM

// per-buffer SMEM layout (bytes)
#define PB_AHI 0
#define PB_ALO 18432
#define PB_BHI 36864
#define PB_BLO 54272
#define BUF_BYTES 71680
#define SMEM_TOTAL (2 * BUF_BYTES)   // 143360

// ---------------- scratch (device globals) ----------------
__device__ __half g_h_hi[(size_t)2 * B_ * G_ * HID_];
__device__ __half g_h_lo[(size_t)2 * B_ * G_ * HID_];
__device__ __half g_f_hi[(size_t)2 * B_ * G_ * FEAT_];
__device__ __half g_f_lo[(size_t)2 * B_ * G_ * FEAT_];
__device__ float  g_part[(size_t)NSPL * 2 * B_ * HID_];    // 67 MB
__device__ float  g_part4[(size_t)NSPL4 * 2 * B_ * FEAT_]; // 33.5 MB
__device__ __half g_hg_hi[(size_t)2 * B_ * HID_];
__device__ __half g_hg_lo[(size_t)2 * B_ * HID_];
__device__ float  g_o[(size_t)2 * B_ * FEAT_];
__device__ float  g_scores[B_];

__device__ __forceinline__ float silu_f(float v) {
    return v / (1.0f + __expf(-v));
}
__device__ __forceinline__ uint32_t smem_to_u32(const void* p) {
    uint32_t a;
    asm("{ .reg .u64 t; cvta.to.shared.u64 t, %1; cvt.u32.u64 %0, t; }"
        : "=r"(a) : "l"(p));
    return a;
}

// ---- family-portable primitives (valid on compute_103) ----
__device__ __forceinline__ void ldsm_x4(uint32_t* r, uint32_t addr) {
    asm volatile("ldmatrix.sync.aligned.m8n8.x4.shared.b16 {%0,%1,%2,%3}, [%4];"
        : "=r"(r[0]), "=r"(r[1]), "=r"(r[2]), "=r"(r[3]) : "r"(addr));
}
__device__ __forceinline__ void ldsm_x2t(uint32_t* r, uint32_t addr) {
    asm volatile("ldmatrix.sync.aligned.m8n8.x2.trans.shared.b16 {%0,%1}, [%2];"
        : "=r"(r[0]), "=r"(r[1]) : "r"(addr));
}
__device__ __forceinline__ void mma_f32(float* d, const uint32_t* a, const uint32_t* b) {
    asm volatile(
        "mma.sync.aligned.m16n8k16.row.col.f32.f16.f16.f32 "
        "{%0,%1,%2,%3}, {%4,%5,%6,%7}, {%8,%9}, {%0,%1,%2,%3};"
        : "+f"(d[0]), "+f"(d[1]), "+f"(d[2]), "+f"(d[3])
        : "r"(a[0]), "r"(a[1]), "r"(a[2]), "r"(a[3]), "r"(b[0]), "r"(b[1]));
}
__device__ __forceinline__ void mma_f16(uint32_t* d, const uint32_t* a, const uint32_t* b) {
    asm volatile(
        "mma.sync.aligned.m16n8k16.row.col.f16.f16.f16.f16 "
        "{%0,%1}, {%2,%3,%4,%5}, {%6,%7}, {%0,%1};"
        : "+r"(d[0]), "+r"(d[1])
        : "r"(a[0]), "r"(a[1]), "r"(a[2]), "r"(a[3]), "r"(b[0]), "r"(b[1]));
}
__device__ __forceinline__ void cp_async16(uint32_t dst, const void* src) {
    asm volatile("cp.async.ca.shared.global [%0], [%1], 16;" :: "r"(dst), "l"(src));
}
__device__ __forceinline__ void cp_async_commit() {
    asm volatile("cp.async.commit_group;" ::: "memory");
}
__device__ __forceinline__ void cp_async_wait0() {
    asm volatile("cp.async.wait_group 0;" ::: "memory");
}

__device__ __forceinline__ void split_f32(float x, __half& hi, __half& lo) {
    hi = __float2half_rn(x);
    lo = __float2half_rn(x - __half2float(hi));
}
__device__ __forceinline__ void split_store2(__half* hi, __half* lo, float v0, float v1) {
    __half h0, l0, h1, l1;
    split_f32(v0, h0, l0); split_f32(v1, h1, l1);
    *reinterpret_cast<__half2*>(hi) = __halves2half2(h0, h1);
    *reinterpret_cast<__half2*>(lo) = __halves2half2(l0, l1);
}
// split 4 floats -> one uint2 (4 halves) each for hi and lo
__device__ __forceinline__ void split4(const float* v, uint32_t* hi2, uint32_t* lo2) {
    __half h0,l0,h1,l1,h2,l2,h3,l3;
    split_f32(v[0], h0, l0); split_f32(v[1], h1, l1);
    split_f32(v[2], h2, l2); split_f32(v[3], h3, l3);
    __half2 a = __halves2half2(h0, h1), b = __halves2half2(h2, h3);
    __half2 c = __halves2half2(l0, l1), d = __halves2half2(l2, l3);
    hi2[0] = *reinterpret_cast<uint32_t*>(&a);
    hi2[1] = *reinterpret_cast<uint32_t*>(&b);
    lo2[0] = *reinterpret_cast<uint32_t*>(&c);
    lo2[1] = *reinterpret_cast<uint32_t*>(&d);
}

// ---------------- GEMM body (512 threads, warp grid 4x4, 32x32/warp, BK=64) ----
template<bool AF16>
__device__ __forceinline__ void gemm_body(
    const float* __restrict__ Af,
    const __half* __restrict__ Ah, const __half* __restrict__ Al, int lda,
    const float* __restrict__ W, int ldw,
    int K, int m0, int n0, float acc[2][4][4])
{
    extern __shared__ char dyn[];
    const uint32_t sb = smem_to_u32(dyn);

    const int tid  = threadIdx.x;
    const int lane = tid & 31;
    const int wid  = tid >> 5;          // 0..15
    const int wm   = (wid >> 2) * 32;
    const int wn   = (wid & 3) * 32;

    // A loader: row = tid/4 (0..127), 16 k-elems from (tid&3)*16
    const int ar = tid >> 2;
    const int as = (tid & 3) << 4;
    // B loader: k-row = tid/8 (0..63), 16 n-elems from (tid&7)*16
    const int kr = tid >> 3;
    const int nb = (tid & 7) << 4;

    const int nk = (K + BK - 1) / BK;

    uint32_t accc[2][4][2];
    #pragma unroll
    for (int mt = 0; mt < 2; ++mt)
        #pragma unroll
        for (int nt = 0; nt < 4; ++nt) {
            accc[mt][nt][0] = 0u; accc[mt][nt][1] = 0u;
            #pragma unroll
            for (int e = 0; e < 4; ++e) acc[mt][nt][e] = 0.0f;
        }

    float ra[16], rb[16];
    const float* Apf = AF16 ? nullptr : (Af + (size_t)(m0 + ar) * lda);

    auto ldgA_f32 = [&](int k0) {
        #pragma unroll
        for (int i = 0; i < 4; ++i) {
            const int kg = k0 + as + i * 4;
            if (kg + 3 < K) {
                float4 v = *reinterpret_cast<const float4*>(Apf + kg);
                ra[i*4+0] = v.x; ra[i*4+1] = v.y; ra[i*4+2] = v.z; ra[i*4+3] = v.w;
            } else {
                #pragma unroll
                for (int j = 0; j < 4; ++j)
                    ra[i*4+j] = (kg + j < K) ? Apf[kg + j] : 0.0f;
            }
        }
    };
    auto cpA_f16 = [&](int k0, int buf) {
        const uint32_t d = sb + buf * BUF_BYTES + (uint32_t)(ar * BKP + as) * 2;
        const size_t go = (size_t)(m0 + ar) * lda + k0 + as;
        cp_async16(d + PB_AHI,      Ah + go);
        cp_async16(d + PB_AHI + 16, Ah + go + 8);
        cp_async16(d + PB_ALO,      Al + go);
        cp_async16(d + PB_ALO + 16, Al + go + 8);
    };
    auto ldgB = [&](int k0) {
        const int kgB = k0 + kr;
        if (kgB < K) {
            const float* Wp = W + (size_t)kgB * ldw + n0 + nb;
            #pragma unroll
            for (int i = 0; i < 4; ++i) {
                float4 v = *reinterpret_cast<const float4*>(Wp + i * 4);
                rb[i*4+0] = v.x; rb[i*4+1] = v.y; rb[i*4+2] = v.z; rb[i*4+3] = v.w;
            }
        } else {
            #pragma unroll
            for (int i = 0; i < 16; ++i) rb[i] = 0.0f;
        }
    };
    auto stA_f32 = [&](int buf) {
        char* base = dyn + buf * BUF_BYTES;
        uint32_t hi2[4], lo2[4];
        split4(ra,     hi2,     lo2);
        split4(ra + 4, hi2 + 2, lo2 + 2);
        *reinterpret_cast<uint4*>(base + PB_AHI + (ar*BKP + as)*2) =
            make_uint4(hi2[0], hi2[1], hi2[2], hi2[3]);
        *reinterpret_cast<uint4*>(base + PB_ALO + (ar*BKP + as)*2) =
            make_uint4(lo2[0], lo2[1], lo2[2], lo2[3]);
        split4(ra + 8,  hi2,     lo2);
        split4(ra + 12, hi2 + 2, lo2 + 2);
        *reinterpret_cast<uint4*>(base + PB_AHI + (ar*BKP + as + 8)*2) =
            make_uint4(hi2[0], hi2[1], hi2[2], hi2[3]);
        *reinterpret_cast<uint4*>(base + PB_ALO + (ar*BKP + as + 8)*2) =
            make_uint4(lo2[0], lo2[1], lo2[2], lo2[3]);
    };
    auto stB = [&](int buf) {
        char* base = dyn + buf * BUF_BYTES;
        uint32_t hi2[4], lo2[4];
        split4(rb,     hi2,     lo2);
        split4(rb + 4, hi2 + 2, lo2 + 2);
        *reinterpret_cast<uint4*>(base + PB_BHI + (kr*BNP + nb)*2) =
            make_uint4(hi2[0], hi2[1], hi2[2], hi2[3]);
        *reinterpret_cast<uint4*>(base + PB_BLO + (kr*BNP + nb)*2) =
            make_uint4(lo2[0], lo2[1], lo2[2], lo2[3]);
        split4(rb + 8,  hi2,     lo2);
        split4(rb + 12, hi2 + 2, lo2 + 2);
        *reinterpret_cast<uint4*>(base + PB_BHI + (kr*BNP + nb + 8)*2) =
            make_uint4(hi2[0], hi2[1], hi2[2], hi2[3]);
        *reinterpret_cast<uint4*>(base + PB_BLO + (kr*BNP + nb + 8)*2) =
            make_uint4(lo2[0], lo2[1], lo2[2], lo2[3]);
    };

    // prologue: stage buffer 0
    if (AF16) cpA_f16(0, 0); else ldgA_f32(0);
    ldgB(0);
    if (!AF16) stA_f32(0);
    stB(0);
    if (AF16) { cp_async_commit(); cp_async_wait0(); }
    __syncthreads();

    for (int t = 0; t < nk; ++t) {
        const int cur = t & 1, nxt = (t + 1) & 1;
        const bool more = (t + 1) < nk;

        if (more) {
            if (AF16) { cpA_f16((t + 1) * BK, nxt); cp_async_commit(); }
            else      { ldgA_f32((t + 1) * BK); }
            ldgB((t + 1) * BK);
        }

        {
            const uint32_t aHiB = sb + cur * BUF_BYTES + PB_AHI;
            const uint32_t aLoB = sb + cur * BUF_BYTES + PB_ALO;
            const uint32_t bHiB = sb + cur * BUF_BYTES + PB_BHI;
            const uint32_t bLoB = sb + cur * BUF_BYTES + PB_BLO;
            const int l = lane & 15;
            #pragma unroll
            for (int ks = 0; ks < 4; ++ks) {
                uint32_t bh[4][2], bl[4][2];
                #pragma unroll
                for (int nt = 0; nt < 4; ++nt) {
                    const uint32_t off =
                        ((uint32_t)(ks * 16 + l) * BNP + wn + nt * 8) * 2;
                    ldsm_x2t(bh[nt], bHiB + off);
                    ldsm_x2t(bl[nt], bLoB + off);
                }
                uint32_t ah[2][4], al[2][4];
                #pragma unroll
                for (int mt = 0; mt < 2; ++mt) {
                    const uint32_t offa =
                        ((uint32_t)(wm + mt * 16 + l) * BKP + ks * 16 + (lane >> 4) * 8) * 2;
                    ldsm_x4(ah[mt], aHiB + offa);
                    ldsm_x4(al[mt], aLoB + offa);
                }
                #pragma unroll
                for (int mt = 0; mt < 2; ++mt)
                    #pragma unroll
                    for (int nt = 0; nt < 4; ++nt)
                        mma_f32(acc[mt][nt], ah[mt], bh[nt]);
                #pragma unroll
                for (int mt = 0; mt < 2; ++mt)
                    #pragma unroll
                    for (int nt = 0; nt < 4; ++nt)
                        mma_f16(accc[mt][nt], ah[mt], bl[nt]);
                #pragma unroll
                for (int mt = 0; mt < 2; ++mt)
                    #pragma unroll
                    for (int nt = 0; nt < 4; ++nt)
                        mma_f16(accc[mt][nt], al[mt], bh[nt]);
            }
        }

        if (more) {
            if (!AF16) stA_f32(nxt);
            stB(nxt);
            if (AF16) cp_async_wait0();
        }
        __syncthreads();
    }

    #pragma unroll
    for (int mt = 0; mt < 2; ++mt)
        #pragma unroll
        for (int nt = 0; nt < 4; ++nt) {
            const __half2 c01 = *reinterpret_cast<const __half2*>(&accc[mt][nt][0]);
            const __half2 c23 = *reinterpret_cast<const __half2*>(&accc[mt][nt][1]);
            acc[mt][nt][0] += __low2float(c01);
            acc[mt][nt][1] += __high2float(c01);
            acc[mt][nt][2] += __low2float(c23);
            acc[mt][nt][3] += __high2float(c23);
        }
}

// ================= stage kernels =================

// stage 1: grouped fc1 (A fp32). grid (2, 8, 32)
__global__ void __launch_bounds__(THREADS, 1) k_fc1g(
    const float* __restrict__ q,  const float* __restrict__ k,
    const float* __restrict__ Wq1, const float* __restrict__ bq1,
    const float* __restrict__ Wk1, const float* __restrict__ bk1)
{
    const int z = blockIdx.z, br = z >> 4, g = z & 15;
    const int m0 = blockIdx.x * BM, n0 = blockIdx.y * BN;

    const float* A    = (br ? k : q) + g * GS_;
    const float* W    = (br ? Wk1 : Wq1) + (size_t)g * GS_ * HID_;
    const float* bias = (br ? bk1 : bq1) + g * HID_;

    float acc[2][4][4];
    gemm_body<false>(A, nullptr, nullptr, G_ * GS_, W, HID_, GS_, m0, n0, acc);

    const int lane = threadIdx.x & 31, wid = threadIdx.x >> 5;
    const int wm = (wid >> 2) * 32, wn = (wid & 3) * 32;
    #pragma unroll
    for (int mt = 0; mt < 2; ++mt) {
        const int r = m0 + wm + mt * 16 + (lane >> 2);
        #pragma unroll
        for (int nt = 0; nt < 4; ++nt) {
            const int c = n0 + wn + nt * 8 + (lane & 3) * 2;
            const float b0 = bias[c], b1 = bias[c + 1];
            const size_t i0 = (size_t)(br * B_ + r) * (G_ * HID_) + (size_t)g * HID_ + c;
            const size_t i1 = i0 + (size_t)8 * (G_ * HID_);
            split_store2(&g_h_hi[i0], &g_h_lo[i0],
                         silu_f(acc[mt][nt][0] + b0), silu_f(acc[mt][nt][1] + b1));
            split_store2(&g_h_hi[i1], &g_h_lo[i1],
                         silu_f(acc[mt][nt][2] + b0), silu_f(acc[mt][nt][3] + b1));
        }
    }
}

// stage 2: grouped fc4 + feature-major interleave (A pre-split). grid (2, 16, 32)
__global__ void __launch_bounds__(THREADS, 1) k_fc4g(
    const float* __restrict__ Wq4, const float* __restrict__ bq4,
    const float* __restrict__ Wk4, const float* __restrict__ bk4)
{
    const int z = blockIdx.z, br = z >> 4, g = z & 15;
    const int m0 = blockIdx.x * BM, n0 = blockIdx.y * BN;

    const __half* Ah  = g_h_hi + (size_t)br * B_ * G_ * HID_ + (size_t)g * HID_;
    const __half* Al  = g_h_lo + (size_t)br * B_ * G_ * HID_ + (size_t)g * HID_;
    const float* W    = (br ? Wk4 : Wq4) + (size_t)g * HID_ * FEAT_;
    const float* bias = (br ? bk4 : bq4) + g * FEAT_;

    float acc[2][4][4];
    gemm_body<true>(nullptr, Ah, Al, G_ * HID_, W, FEAT_, HID_, m0, n0, acc);

    const int lane = threadIdx.x & 31, wid = threadIdx.x >> 5;
    const int wm = (wid >> 2) * 32, wn = (wid & 3) * 32;
    #pragma unroll
    for (int mt = 0; mt < 2; ++mt) {
        const int r = m0 + wm + mt * 16 + (lane >> 2);
        const size_t rb0 = (size_t)(br * B_ + r)     * (G_ * FEAT_) + g;
        const size_t rb1 = (size_t)(br * B_ + r + 8) * (G_ * FEAT_) + g;
        #pragma unroll
        for (int nt = 0; nt < 4; ++nt) {
            const int c = n0 + wn + nt * 8 + (lane & 3) * 2;
            const float b0 = bias[c], b1 = bias[c + 1];
            const float v0 = silu_f(acc[mt][nt][0] + b0);
            const float v1 = silu_f(acc[mt][nt][1] + b1);
            const float v2 = silu_f(acc[mt][nt][2] + b0);
            const float v3 = silu_f(acc[mt][nt][3] + b1);
            __half h, l;
            split_f32(v0, h, l); g_f_hi[rb0 + (size_t)c * G_] = h;       g_f_lo[rb0 + (size_t)c * G_] = l;
            split_f32(v1, h, l); g_f_hi[rb0 + (size_t)(c + 1) * G_] = h; g_f_lo[rb0 + (size_t)(c + 1) * G_] = l;
            split_f32(v2, h, l); g_f_hi[rb1 + (size_t)c * G_] = h;       g_f_lo[rb1 + (size_t)c * G_] = l;
            split_f32(v3, h, l); g_f_hi[rb1 + (size_t)(c + 1) * G_] = h; g_f_lo[rb1 + (size_t)(c + 1) * G_] = l;
        }
    }
}

// stage 3: global fc1 split-K. grid (4, 8, NSPL=32)
__global__ void __launch_bounds__(THREADS, 1) k_gf1(const float* __restrict__ Wg1)
{
    const int s = blockIdx.z;
    const int m0 = blockIdx.x * BM, n0 = blockIdx.y * BN;

    const __half* Ah = g_f_hi + (size_t)s * KSPL;
    const __half* Al = g_f_lo + (size_t)s * KSPL;
    const float*  W  = Wg1 + (size_t)s * KSPL * HID_;

    float acc[2][4][4];
    gemm_body<true>(nullptr, Ah, Al, G_ * FEAT_, W, HID_, KSPL, m0, n0, acc);

    const int lane = threadIdx.x & 31, wid = threadIdx.x >> 5;
    const int wm = (wid >> 2) * 32, wn = (wid & 3) * 32;
    float* P = g_part + (size_t)s * (2 * B_ * HID_);
    #pragma unroll
    for (int mt = 0; mt < 2; ++mt) {
        const int r = m0 + wm + mt * 16 + (lane >> 2);
        #pragma unroll
        for (int nt = 0; nt < 4; ++nt) {
            const int c = n0 + wn + nt * 8 + (lane & 3) * 2;
            P[(size_t)r * HID_ + c]           = acc[mt][nt][0];
            P[(size_t)r * HID_ + c + 1]       = acc[mt][nt][1];
            P[(size_t)(r + 8) * HID_ + c]     = acc[mt][nt][2];
            P[(size_t)(r + 8) * HID_ + c + 1] = acc[mt][nt][3];
        }
    }
}

// reduce NSPL partials + bias + silu -> pre-split g_hg
__global__ void __launch_bounds__(256) k_reduce_silu(const float* __restrict__ bg1)
{
    const int idx = blockIdx.x * blockDim.x + threadIdx.x;
    if (idx >= 2 * B_ * HID_) return;
    const int col = idx & (HID_ - 1);
    float v = bg1[col];
    #pragma unroll
    for (int s = 0; s < NSPL; ++s)
        v += g_part[(size_t)s * (2 * B_ * HID_) + idx];
    v = silu_f(v);
    __half h, l;
    split_f32(v, h, l);
    g_hg_hi[idx] = h;
    g_hg_lo[idx] = l;
}

// stage 4: global fc4 split-K (A pre-split). grid (4, 16, NSPL4=8)
__global__ void __launch_bounds__(THREADS, 1) k_gf4(const float* __restrict__ Wg4)
{
    const int s = blockIdx.z;
    const int m0 = blockIdx.x * BM, n0 = blockIdx.y * BN;

    const __half* Ah = g_hg_hi + (size_t)s * KSPL4;
    const __half* Al = g_hg_lo + (size_t)s * KSPL4;
    const float*  W  = Wg4 + (size_t)s * KSPL4 * FEAT_;

    float acc[2][4][4];
    gemm_body<true>(nullptr, Ah, Al, HID_, W, FEAT_, KSPL4, m0, n0, acc);

    const int lane = threadIdx.x & 31, wid = threadIdx.x >> 5;
    const int wm = (wid >> 2) * 32, wn = (wid & 3) * 32;
    float* P = g_part4 + (size_t)s * (2 * B_ * FEAT_);
    #pragma unroll
    for (int mt = 0; mt < 2; ++mt) {
        const int r = m0 + wm + mt * 16 + (lane >> 2);
        #pragma unroll
        for (int nt = 0; nt < 4; ++nt) {
            const int c = n0 + wn + nt * 8 + (lane & 3) * 2;
            P[(size_t)r * FEAT_ + c]           = acc[mt][nt][0];
            P[(size_t)r * FEAT_ + c + 1]       = acc[mt][nt][1];
            P[(size_t)(r + 8) * FEAT_ + c]     = acc[mt][nt][2];
            P[(size_t)(r + 8) * FEAT_ + c + 1] = acc[mt][nt][3];
        }
    }
}

// reduce NSPL4 partials + bias + silu -> g_o
__global__ void __launch_bounds__(256) k_reduce4(const float* __restrict__ bg4)
{
    const int idx = blockIdx.x * blockDim.x + threadIdx.x;
    if (idx >= 2 * B_ * FEAT_) return;
    const int col = idx & (FEAT_ - 1);
    float v = bg4[col];
    #pragma unroll
    for (int s = 0; s < NSPL4; ++s)
        v += g_part4[(size_t)s * (2 * B_ * FEAT_) + idx];
    g_o[idx] = silu_f(v);
}

// stage 5: per-batch dot
__global__ void __launch_bounds__(256) k_dot()
{
    const int b = blockIdx.x;
    const int t = threadIdx.x;
    const float* qo = g_o + (size_t)b * FEAT_;
    const float* ko = g_o + (size_t)(B_ + b) * FEAT_;
    float s = 0.0f;
    for (int i = t; i < FEAT_; i += 256)
        s = fmaf(qo[i], ko[i], s);
    __shared__ float sh[256];
    sh[t] = s;
    __syncthreads();
    for (int off = 128; off > 0; off >>= 1) {
        if (t < off) sh[t] += sh[t + off];
        __syncthreads();
    }
    if (t == 0) g_scores[b] = sh[0];
}

// stage 6: softmax over batch
__global__ void __launch_bounds__(256) k_softmax(float* __restrict__ out)
{
    const int t = threadIdx.x;
    __shared__ float sh[256];
    float v = g_scores[t];
    sh[t] = v;
    __syncthreads();
    for (int off = 128; off > 0; off >>= 1) {
        if (t < off) sh[t] = fmaxf(sh[t], sh[t + off]);
        __syncthreads();
    }
    const float m = sh[0];
    __syncthreads();
    const float e = expf(v - m);
    sh[t] = e;
    __syncthreads();
    for (int off = 128; off > 0; off >>= 1) {
        if (t < off) sh[t] += sh[t + off];
        __syncthreads();
    }
    out[t] = e / sh[0];
}

// ================= launch =================
extern "C" void kernel_launch(void* const* d_in, const int* in_sizes, int n_in,
                              void* d_out, int out_size)
{
    const float* q   = (const float*)d_in[0];
    const float* k   = (const float*)d_in[1];
    const float* Wq1 = (const float*)d_in[2];
    const float* bq1 = (const float*)d_in[3];
    const float* Wq4 = (const float*)d_in[4];
    const float* bq4 = (const float*)d_in[5];
    const float* Wk1 = (const float*)d_in[6];
    const float* bk1 = (const float*)d_in[7];
    const float* Wk4 = (const float*)d_in[8];
    const float* bk4 = (const float*)d_in[9];
    const float* Wg1 = (const float*)d_in[10];
    const float* bg1 = (const float*)d_in[11];
    const float* Wg4 = (const float*)d_in[12];
    const float* bg4 = (const float*)d_in[13];
    float* out = (float*)d_out;

    cudaFuncSetAttribute(k_fc1g, cudaFuncAttributeMaxDynamicSharedMemorySize, SMEM_TOTAL);
    cudaFuncSetAttribute(k_fc4g, cudaFuncAttributeMaxDynamicSharedMemorySize, SMEM_TOTAL);
    cudaFuncSetAttribute(k_gf1,  cudaFuncAttributeMaxDynamicSharedMemorySize, SMEM_TOTAL);
    cudaFuncSetAttribute(k_gf4,  cudaFuncAttributeMaxDynamicSharedMemorySize, SMEM_TOTAL);

    k_fc1g<<<dim3(2, 8, 2 * G_),   THREADS, SMEM_TOTAL>>>(q, k, Wq1, bq1, Wk1, bk1);
    k_fc4g<<<dim3(2, 16, 2 * G_),  THREADS, SMEM_TOTAL>>>(Wq4, bq4, Wk4, bk4);
    k_gf1<<<dim3(4, 8, NSPL),      THREADS, SMEM_TOTAL>>>(Wg1);
    k_reduce_silu<<<(2 * B_ * HID_) / 256, 256>>>(bg1);
    k_gf4<<<dim3(4, 16, NSPL4),    THREADS, SMEM_TOTAL>>>(Wg4);
    k_reduce4<<<(2 * B_ * FEAT_) / 256, 256>>>(bg4);
    k_dot<<<B_, 256>>>();
    k_softmax<<<1, 256>>>(out);
}